// round 1
// baseline (speedup 1.0000x reference)
#include <cuda_runtime.h>
#include <math.h>

#define SEQ    2048
#define DM     2048
#define NH     16
#define HD     128
#define NB     2
#define MTOT   (NB * SEQ)          // 4096

// ---------------- scratch (device globals: allocation-free rule) ------------
static __device__ float g_q [(size_t)MTOT * DM];            // 32 MB
static __device__ float g_k [(size_t)MTOT * DM];            // 32 MB
static __device__ float g_v [(size_t)MTOT * DM];            // 32 MB
static __device__ float g_ao[(size_t)MTOT * DM];            // 32 MB
static __device__ float g_p [2ULL * NH * SEQ * SEQ];        // 512 MB scores/probs
static __device__ float g_cos[SEQ * (HD / 2)];
static __device__ float g_sin[SEQ * (HD / 2)];

// ---------------- RoPE table (match jnp: fp32 angle, accurate trig) ---------
__global__ void rope_table_kernel()
{
    int s = blockIdx.x;          // 0..2047
    int i = threadIdx.x;         // 0..63
    double e    = ((double)(2 * i)) / (double)HD;
    double powd = pow(10000.0, e);
    float  invf = (float)(1.0 / powd);          // fp32 inv_freq (as jnp)
    float  fr   = (float)s * invf;              // fp32-rounded angle (as jnp)
    double a    = (double)fr;
    g_cos[s * (HD / 2) + i] = (float)cos(a);
    g_sin[s * (HD / 2) + i] = (float)sin(a);
}

__global__ __launch_bounds__(256) void rope_apply_kernel()
{
    size_t idx = (size_t)blockIdx.x * 256 + threadIdx.x;   // < MTOT*1024
    int    i   = (int)(idx & 63);                          // pair index within head
    size_t cp  = idx & 1023;                               // float2 col within row
    size_t m   = idx >> 10;                                // global row (b*S+s)
    int    s   = (int)(m & (SEQ - 1));
    float  c   = g_cos[s * (HD / 2) + i];
    float  sn  = g_sin[s * (HD / 2) + i];
    size_t off = m * (DM / 2) + cp;

    float2* qp = (float2*)g_q;
    float2  v  = qp[off];
    qp[off] = make_float2(v.x * c - v.y * sn, v.x * sn + v.y * c);

    float2* kp = (float2*)g_k;
    v = kp[off];
    kp[off] = make_float2(v.x * c - v.y * sn, v.x * sn + v.y * c);
}

// ---------------- generic NT SGEMM: C[m,n] = sum_k A[m,k] * B[n,k] ----------
// M tiles on blockIdx.y, N tiles on blockIdx.x, weight select on blockIdx.z.
// All leading dims are DM (=2048). 128x128x16 tile, 8x8 per thread.
__global__ __launch_bounds__(256, 2) void gemm_nt_kernel(
    const float* __restrict__ A,
    const float* __restrict__ B0, const float* __restrict__ B1, const float* __restrict__ B2,
    float* __restrict__ C0, float* __restrict__ C1, float* __restrict__ C2,
    int Kdim)
{
    const float* Bw = (blockIdx.z == 0) ? B0 : (blockIdx.z == 1) ? B1 : B2;
    float*       Cw = (blockIdx.z == 0) ? C0 : (blockIdx.z == 1) ? C1 : C2;

    __shared__ __align__(16) float As[16][132];
    __shared__ __align__(16) float Bs[16][132];

    const int t  = threadIdx.x;
    const int tx = t & 15, ty = t >> 4;
    const size_t m0 = (size_t)blockIdx.y * 128;
    const size_t n0 = (size_t)blockIdx.x * 128;
    const float* Ab = A  + m0 * DM;
    const float* Bb = Bw + n0 * DM;

    float acc[8][8];
#pragma unroll
    for (int i = 0; i < 8; i++)
#pragma unroll
        for (int j = 0; j < 8; j++) acc[i][j] = 0.f;

    for (int kt = 0; kt < Kdim; kt += 16) {
#pragma unroll
        for (int u = 0; u < 2; u++) {
            int idx = t + u * 256;
            int r   = idx >> 2;
            int k4  = (idx & 3) << 2;
            float4 av = *(const float4*)(Ab + (size_t)r * DM + kt + k4);
            As[k4 + 0][r] = av.x; As[k4 + 1][r] = av.y;
            As[k4 + 2][r] = av.z; As[k4 + 3][r] = av.w;
            float4 bv = *(const float4*)(Bb + (size_t)r * DM + kt + k4);
            Bs[k4 + 0][r] = bv.x; Bs[k4 + 1][r] = bv.y;
            Bs[k4 + 2][r] = bv.z; Bs[k4 + 3][r] = bv.w;
        }
        __syncthreads();
#pragma unroll
        for (int k = 0; k < 16; k++) {
            float4 a0 = *(const float4*)&As[k][ty * 8];
            float4 a1 = *(const float4*)&As[k][ty * 8 + 4];
            float4 b0 = *(const float4*)&Bs[k][tx * 8];
            float4 b1 = *(const float4*)&Bs[k][tx * 8 + 4];
            float a[8] = {a0.x, a0.y, a0.z, a0.w, a1.x, a1.y, a1.z, a1.w};
            float b[8] = {b0.x, b0.y, b0.z, b0.w, b1.x, b1.y, b1.z, b1.w};
#pragma unroll
            for (int i = 0; i < 8; i++)
#pragma unroll
                for (int j = 0; j < 8; j++)
                    acc[i][j] = fmaf(a[i], b[j], acc[i][j]);
        }
        __syncthreads();
    }

#pragma unroll
    for (int i = 0; i < 8; i++) {
        float* crow = Cw + (m0 + ty * 8 + i) * DM + n0 + tx * 8;
        *(float4*)(crow)     = make_float4(acc[i][0], acc[i][1], acc[i][2], acc[i][3]);
        *(float4*)(crow + 4) = make_float4(acc[i][4], acc[i][5], acc[i][6], acc[i][7]);
    }
}

// ---------------- scores = (Q_h @ K_h^T) / sqrt(hd), causal tile skip -------
// grid: (16 n-tiles, 16 m-tiles, 32 b*h)
__global__ __launch_bounds__(256, 2) void scores_kernel()
{
    const int bn = blockIdx.x, bm = blockIdx.y, z = blockIdx.z;
    if (bn > bm) return;                        // fully masked tile
    const int b = z >> 4, h = z & 15;
    const float* Ab = g_q + ((size_t)(b * SEQ + bm * 128)) * DM + h * HD;
    const float* Bb = g_k + ((size_t)(b * SEQ + bn * 128)) * DM + h * HD;
    float*       Cb = g_p + (size_t)z * SEQ * SEQ + (size_t)(bm * 128) * SEQ + bn * 128;

    __shared__ __align__(16) float As[16][132];
    __shared__ __align__(16) float Bs[16][132];

    const int t  = threadIdx.x;
    const int tx = t & 15, ty = t >> 4;

    float acc[8][8];
#pragma unroll
    for (int i = 0; i < 8; i++)
#pragma unroll
        for (int j = 0; j < 8; j++) acc[i][j] = 0.f;

    for (int kt = 0; kt < HD; kt += 16) {
#pragma unroll
        for (int u = 0; u < 2; u++) {
            int idx = t + u * 256;
            int r   = idx >> 2;
            int k4  = (idx & 3) << 2;
            float4 av = *(const float4*)(Ab + (size_t)r * DM + kt + k4);
            As[k4 + 0][r] = av.x; As[k4 + 1][r] = av.y;
            As[k4 + 2][r] = av.z; As[k4 + 3][r] = av.w;
            float4 bv = *(const float4*)(Bb + (size_t)r * DM + kt + k4);
            Bs[k4 + 0][r] = bv.x; Bs[k4 + 1][r] = bv.y;
            Bs[k4 + 2][r] = bv.z; Bs[k4 + 3][r] = bv.w;
        }
        __syncthreads();
#pragma unroll
        for (int k = 0; k < 16; k++) {
            float4 a0 = *(const float4*)&As[k][ty * 8];
            float4 a1 = *(const float4*)&As[k][ty * 8 + 4];
            float4 b0 = *(const float4*)&Bs[k][tx * 8];
            float4 b1 = *(const float4*)&Bs[k][tx * 8 + 4];
            float a[8] = {a0.x, a0.y, a0.z, a0.w, a1.x, a1.y, a1.z, a1.w};
            float b[8] = {b0.x, b0.y, b0.z, b0.w, b1.x, b1.y, b1.z, b1.w};
#pragma unroll
            for (int i = 0; i < 8; i++)
#pragma unroll
                for (int j = 0; j < 8; j++)
                    acc[i][j] = fmaf(a[i], b[j], acc[i][j]);
        }
        __syncthreads();
    }

    const float scale = 0.088388347648318447f;  // 1/sqrt(128)
#pragma unroll
    for (int i = 0; i < 8; i++) {
        float* crow = Cb + (size_t)(ty * 8 + i) * SEQ + tx * 8;
        *(float4*)(crow)     = make_float4(acc[i][0] * scale, acc[i][1] * scale,
                                           acc[i][2] * scale, acc[i][3] * scale);
        *(float4*)(crow + 4) = make_float4(acc[i][4] * scale, acc[i][5] * scale,
                                           acc[i][6] * scale, acc[i][7] * scale);
    }
}

// ---------------- causal row softmax in place; zero-fills masked tail -------
// grid: (SEQ rows, 32 b*h), 256 threads
__global__ __launch_bounds__(256) void softmax_kernel()
{
    const int q = blockIdx.x, z = blockIdx.y;
    float* row = g_p + (size_t)z * SEQ * SEQ + (size_t)q * SEQ;
    const int L = q + 1;
    __shared__ float red[256];
    const int tid = threadIdx.x;

    float m = -1e30f;
    for (int k = tid; k < L; k += 256) m = fmaxf(m, row[k]);
    red[tid] = m; __syncthreads();
    for (int s = 128; s > 0; s >>= 1) {
        if (tid < s) red[tid] = fmaxf(red[tid], red[tid + s]);
        __syncthreads();
    }
    const float rowmax = red[0];
    __syncthreads();

    float sum = 0.f;
    for (int k = tid; k < L; k += 256) {
        float e = __expf(row[k] - rowmax);
        row[k] = e;
        sum += e;
    }
    red[tid] = sum; __syncthreads();
    for (int s = 128; s > 0; s >>= 1) {
        if (tid < s) red[tid] += red[tid + s];
        __syncthreads();
    }
    const float inv = 1.0f / red[0];

    for (int k = tid; k < L; k += 256) row[k] *= inv;
    for (int k = L + tid; k < SEQ; k += 256) row[k] = 0.f;   // exp(-1e9) == 0 exactly
}

// ---------------- O_h = P_h @ V_h (NN; causal K bound) ----------------------
// grid: (16 q-tiles, 32 b*h)
__global__ __launch_bounds__(256, 2) void pv_kernel()
{
    const int bm = blockIdx.x, z = blockIdx.y;
    const int b = z >> 4, h = z & 15;
    const float* Ab    = g_p + (size_t)z * SEQ * SEQ + (size_t)(bm * 128) * SEQ;
    const float* Bbase = g_v + (size_t)(b * SEQ) * DM + h * HD;
    float*       Cb    = g_ao + (size_t)(b * SEQ + bm * 128) * DM + h * HD;
    const int Kdim = (bm + 1) * 128;            // P beyond this is exactly 0

    __shared__ __align__(16) float As[16][132];
    __shared__ __align__(16) float Bs[16][132];

    const int t  = threadIdx.x;
    const int tx = t & 15, ty = t >> 4;

    float acc[8][8];
#pragma unroll
    for (int i = 0; i < 8; i++)
#pragma unroll
        for (int j = 0; j < 8; j++) acc[i][j] = 0.f;

    for (int kt = 0; kt < Kdim; kt += 16) {
#pragma unroll
        for (int u = 0; u < 2; u++) {
            int idx = t + u * 256;
            int r   = idx >> 2;
            int k4  = (idx & 3) << 2;
            float4 av = *(const float4*)(Ab + (size_t)r * SEQ + kt + k4);
            As[k4 + 0][r] = av.x; As[k4 + 1][r] = av.y;
            As[k4 + 2][r] = av.z; As[k4 + 3][r] = av.w;
            // B is N-contiguous: load rows of V directly
            int rb = idx >> 5;                  // 0..15 (k within tile)
            int n4 = (idx & 31) << 2;           // 0..124
            float4 bv = *(const float4*)(Bbase + (size_t)(kt + rb) * DM + n4);
            *(float4*)&Bs[rb][n4] = bv;
        }
        __syncthreads();
#pragma unroll
        for (int k = 0; k < 16; k++) {
            float4 a0 = *(const float4*)&As[k][ty * 8];
            float4 a1 = *(const float4*)&As[k][ty * 8 + 4];
            float4 b0 = *(const float4*)&Bs[k][tx * 8];
            float4 b1 = *(const float4*)&Bs[k][tx * 8 + 4];
            float a[8] = {a0.x, a0.y, a0.z, a0.w, a1.x, a1.y, a1.z, a1.w};
            float b[8] = {b0.x, b0.y, b0.z, b0.w, b1.x, b1.y, b1.z, b1.w};
#pragma unroll
            for (int i = 0; i < 8; i++)
#pragma unroll
                for (int j = 0; j < 8; j++)
                    acc[i][j] = fmaf(a[i], b[j], acc[i][j]);
        }
        __syncthreads();
    }

#pragma unroll
    for (int i = 0; i < 8; i++) {
        float* crow = Cb + (size_t)(ty * 8 + i) * DM + tx * 8;
        *(float4*)(crow)     = make_float4(acc[i][0], acc[i][1], acc[i][2], acc[i][3]);
        *(float4*)(crow + 4) = make_float4(acc[i][4], acc[i][5], acc[i][6], acc[i][7]);
    }
}

// ---------------- launch --------------------------------------------------
extern "C" void kernel_launch(void* const* d_in, const int* in_sizes, int n_in,
                              void* d_out, int out_size)
{
    const float* x  = (const float*)d_in[0];
    // d_in[1] is the mask: causality handled analytically (exact match)
    const float* Wq = (const float*)d_in[2];
    const float* Wk = (const float*)d_in[3];
    const float* Wv = (const float*)d_in[4];
    const float* Wo = (const float*)d_in[5];
    float* out = (float*)d_out;

    float *pq, *pk, *pvv, *pao;
    cudaGetSymbolAddress((void**)&pq,  g_q);
    cudaGetSymbolAddress((void**)&pk,  g_k);
    cudaGetSymbolAddress((void**)&pvv, g_v);
    cudaGetSymbolAddress((void**)&pao, g_ao);

    rope_table_kernel<<<SEQ, HD / 2>>>();
    gemm_nt_kernel<<<dim3(16, 32, 3), 256>>>(x, Wq, Wk, Wv, pq, pk, pvv, DM);
    rope_apply_kernel<<<(MTOT * (DM / 2)) / 256, 256>>>();
    scores_kernel<<<dim3(16, 16, 32), 256>>>();
    softmax_kernel<<<dim3(SEQ, 32), 256>>>();
    pv_kernel<<<dim3(16, 32), 256>>>();
    gemm_nt_kernel<<<dim3(16, 32, 1), 256>>>(pao, Wo, Wo, Wo, out, out, out, DM);
}

// round 6
// speedup vs baseline: 1.6041x; 1.6041x over previous
#include <cuda_runtime.h>
#include <cuda_bf16.h>
#include <math.h>
#include <stdint.h>

#define SEQ    2048
#define DM     2048
#define NH     16
#define HD     128
#define NB     2
#define MTOT   (NB * SEQ)          // 4096
#define K3     4096                // split width: [hi(2048) | lo(2048)]
#define SA     40                  // smem row stride in bf16 (80B, conflict-free)

// ---------------- scratch (device globals: allocation-free rule) ------------
static __device__ float g_q [(size_t)MTOT * DM];            // 32 MB
static __device__ float g_k [(size_t)MTOT * DM];            // 32 MB
static __device__ float g_v [(size_t)MTOT * DM];            // 32 MB
static __device__ float g_ao[(size_t)MTOT * DM];            // 32 MB
static __device__ float g_p [2ULL * NH * SEQ * SEQ];        // 512 MB scores/probs
static __device__ float g_cos[SEQ * (HD / 2)];
static __device__ float g_sin[SEQ * (HD / 2)];
static __device__ __nv_bfloat16 g_xs [(size_t)MTOT * K3];   // 32 MB  x split
static __device__ __nv_bfloat16 g_ws [4ULL * DM * K3];      // 64 MB  Wq/Wk/Wv/Wo split
static __device__ __nv_bfloat16 g_aos[(size_t)MTOT * K3];   // 32 MB  attn-out split

// ---------------- PTX helpers (all baseline ISA, no 'a' features) -----------
__device__ __forceinline__ uint32_t smem_u32(const void* p) {
    uint32_t a;
    asm("{ .reg .u64 t; cvta.to.shared.u64 t, %1; cvt.u32.u64 %0, t; }"
        : "=r"(a) : "l"(p));
    return a;
}

__device__ __forceinline__ void cp16(uint32_t saddr, const void* g) {
    asm volatile("cp.async.cg.shared.global [%0], [%1], 16;"
                 :: "r"(saddr), "l"(g));
}

__device__ __forceinline__ void ldm_x4(uint32_t addr, uint32_t& r0, uint32_t& r1,
                                       uint32_t& r2, uint32_t& r3) {
    asm volatile("ldmatrix.sync.aligned.m8n8.x4.shared.b16 {%0,%1,%2,%3}, [%4];"
                 : "=r"(r0), "=r"(r1), "=r"(r2), "=r"(r3) : "r"(addr));
}

__device__ __forceinline__ void mma_bf16(float* c, const uint32_t* a, const uint32_t* b) {
    asm volatile(
        "mma.sync.aligned.m16n8k16.row.col.f32.bf16.bf16.f32 "
        "{%0,%1,%2,%3}, {%4,%5,%6,%7}, {%8,%9}, {%0,%1,%2,%3};"
        : "+f"(c[0]), "+f"(c[1]), "+f"(c[2]), "+f"(c[3])
        : "r"(a[0]), "r"(a[1]), "r"(a[2]), "r"(a[3]), "r"(b[0]), "r"(b[1]));
}

// ---------------- RoPE table (match jnp: fp32 angle, accurate trig) ---------
__global__ void rope_table_kernel()
{
    int s = blockIdx.x;          // 0..2047
    int i = threadIdx.x;         // 0..63
    double e    = ((double)(2 * i)) / (double)HD;
    double powd = pow(10000.0, e);
    float  invf = (float)(1.0 / powd);
    float  fr   = (float)s * invf;
    double a    = (double)fr;
    g_cos[s * (HD / 2) + i] = (float)cos(a);
    g_sin[s * (HD / 2) + i] = (float)sin(a);
}

__global__ __launch_bounds__(256) void rope_apply_kernel()
{
    size_t idx = (size_t)blockIdx.x * 256 + threadIdx.x;
    int    i   = (int)(idx & 63);
    size_t cp  = idx & 1023;
    size_t m   = idx >> 10;
    int    s   = (int)(m & (SEQ - 1));
    float  c   = g_cos[s * (HD / 2) + i];
    float  sn  = g_sin[s * (HD / 2) + i];
    size_t off = m * (DM / 2) + cp;

    float2* qp = (float2*)g_q;
    float2  v  = qp[off];
    qp[off] = make_float2(v.x * c - v.y * sn, v.x * sn + v.y * c);

    float2* kp = (float2*)g_k;
    v = kp[off];
    kp[off] = make_float2(v.x * c - v.y * sn, v.x * sn + v.y * c);
}

// ---------------- bf16 hi/lo split: src [R x 2048] -> dst [R x 4096] --------
__global__ __launch_bounds__(256) void split_kernel(const float* __restrict__ src,
                                                    __nv_bfloat16* __restrict__ dst,
                                                    int n)
{
    int i = blockIdx.x * 256 + threadIdx.x;
    if (i >= n) return;
    size_t r  = (size_t)(i >> 11);
    int    cc = i & 2047;
    float v = src[i];
    __nv_bfloat16 hi = __float2bfloat16(v);            // RN
    float hv = __bfloat162float(hi);
    __nv_bfloat16 lo = __float2bfloat16(v - hv);
    dst[r * K3 + cc]        = hi;
    dst[r * K3 + 2048 + cc] = lo;
}

// ---------------- mma.sync bf16x3 GEMM: C[m,n] = sum_k A[m,k] B[n,k] --------
// A split [M x 4096], B split [2048 x 4096]; 3 logical K-segments:
// seg0: Ahi*Bhi, seg1: Ahi*Blo, seg2: Alo*Bhi => 192 chunks of K=32.
// 128x128 CTA tile, 8 warps each 64x32, double-buffered cp.async SMEM.
__global__ void __launch_bounds__(256) mma_gemm_kernel(
    const __nv_bfloat16* __restrict__ A,
    const __nv_bfloat16* __restrict__ B0, const __nv_bfloat16* __restrict__ B1,
    const __nv_bfloat16* __restrict__ B2,
    float* __restrict__ C0, float* __restrict__ C1, float* __restrict__ C2)
{
    const __nv_bfloat16* Bw = (blockIdx.z == 0) ? B0 : (blockIdx.z == 1) ? B1 : B2;
    float*               Cw = (blockIdx.z == 0) ? C0 : (blockIdx.z == 1) ? C1 : C2;

    __shared__ __align__(16) __nv_bfloat16 sm_a[2][128 * SA];
    __shared__ __align__(16) __nv_bfloat16 sm_b[2][128 * SA];

    const int t    = threadIdx.x;
    const int wid  = t >> 5;
    const int lane = t & 31;
    const int wm0  = (wid >> 2) * 64;    // warp rows: 0 or 64
    const int wn0  = (wid & 3) * 32;     // warp cols: 0/32/64/96

    const size_t m0 = (size_t)blockIdx.y * 128;
    const size_t n0 = (size_t)blockIdx.x * 128;
    const __nv_bfloat16* Ab = A  + m0 * K3;
    const __nv_bfloat16* Bb = Bw + n0 * K3;

    const uint32_t sa0 = smem_u32(&sm_a[0][0]);
    const uint32_t sa1 = smem_u32(&sm_a[1][0]);
    const uint32_t sb0 = smem_u32(&sm_b[0][0]);
    const uint32_t sb1 = smem_u32(&sm_b[1][0]);

    // 512 load slots: idx -> row = idx>>2 (0..127), seg = idx&3 (16B each)
    const int lr0 = t >> 2, ls0 = t & 3;
    const int lr1 = lr0 + 64, ls1 = ls0;

    float acc[4][4][4];
#pragma unroll
    for (int i = 0; i < 4; i++)
#pragma unroll
        for (int j = 0; j < 4; j++)
#pragma unroll
            for (int r = 0; r < 4; r++) acc[i][j][r] = 0.f;

    // ldmatrix address components (fixed per thread)
    const int atile = lane >> 3;             // 0..3
    const int arow8 = (atile & 1) * 8;       // A: row offset within 16
    const int akof  = (atile >> 1) * 8;      // A: k offset within 16
    const int bnof  = (atile >> 1) * 8;      // B: n offset within 16
    const int bkof  = (atile & 1) * 8;       // B: k offset within 16
    const int l8    = lane & 7;

    const int NC = 192;
    // prologue: load chunk 0 into buf 0
    {
        cp16(sa0 + (lr0 * SA + ls0 * 8) * 2, Ab + (size_t)lr0 * K3 + ls0 * 8);
        cp16(sb0 + (lr0 * SA + ls0 * 8) * 2, Bb + (size_t)lr0 * K3 + ls0 * 8);
        cp16(sa0 + (lr1 * SA + ls1 * 8) * 2, Ab + (size_t)lr1 * K3 + ls1 * 8);
        cp16(sb0 + (lr1 * SA + ls1 * 8) * 2, Bb + (size_t)lr1 * K3 + ls1 * 8);
        asm volatile("cp.async.commit_group;" ::: "memory");
    }

    for (int c = 0; c < NC; ++c) {
        const int buf = c & 1;
        const int cn  = c + 1;
        if (cn < NC) {
            const int nbuf = cn & 1;
            const uint32_t na = nbuf ? sa1 : sa0;
            const uint32_t nb = nbuf ? sb1 : sb0;
            const int seg = cn >> 6;
            const int kin = (cn & 63) << 5;
            const int kA  = ((seg == 2) ? 2048 : 0) + kin;
            const int kB  = ((seg == 1) ? 2048 : 0) + kin;
            cp16(na + (lr0 * SA + ls0 * 8) * 2, Ab + (size_t)lr0 * K3 + kA + ls0 * 8);
            cp16(nb + (lr0 * SA + ls0 * 8) * 2, Bb + (size_t)lr0 * K3 + kB + ls0 * 8);
            cp16(na + (lr1 * SA + ls1 * 8) * 2, Ab + (size_t)lr1 * K3 + kA + ls1 * 8);
            cp16(nb + (lr1 * SA + ls1 * 8) * 2, Bb + (size_t)lr1 * K3 + kB + ls1 * 8);
            asm volatile("cp.async.commit_group;" ::: "memory");
            asm volatile("cp.async.wait_group 1;" ::: "memory");
        } else {
            asm volatile("cp.async.wait_group 0;" ::: "memory");
        }
        __syncthreads();

        const uint32_t ab = buf ? sa1 : sa0;
        const uint32_t bb = buf ? sb1 : sb0;

#pragma unroll
        for (int kk = 0; kk < 32; kk += 16) {
            uint32_t af[4][4], bf[4][2];
#pragma unroll
            for (int i = 0; i < 4; ++i) {
                int row = wm0 + 16 * i + arow8 + l8;
                ldm_x4(ab + (uint32_t)(row * SA + kk + akof) * 2,
                       af[i][0], af[i][1], af[i][2], af[i][3]);
            }
#pragma unroll
            for (int jp = 0; jp < 2; ++jp) {
                int n = wn0 + 16 * jp + bnof + l8;
                uint32_t r0, r1, r2, r3;
                ldm_x4(bb + (uint32_t)(n * SA + kk + bkof) * 2, r0, r1, r2, r3);
                bf[2 * jp + 0][0] = r0; bf[2 * jp + 0][1] = r1;
                bf[2 * jp + 1][0] = r2; bf[2 * jp + 1][1] = r3;
            }
#pragma unroll
            for (int i = 0; i < 4; ++i)
#pragma unroll
                for (int j = 0; j < 4; ++j)
                    mma_bf16(acc[i][j], af[i], bf[j]);
        }
        __syncthreads();
    }

    // epilogue: c0,c1 at (row, col..col+1); c2,c3 at (row+8, col..col+1)
    const int rbase = lane >> 2;
    const int cbase = (lane & 3) * 2;
#pragma unroll
    for (int i = 0; i < 4; ++i) {
#pragma unroll
        for (int j = 0; j < 4; ++j) {
            size_t row = m0 + wm0 + 16 * i + rbase;
            size_t col = n0 + wn0 + 8 * j + cbase;
            *(float2*)(Cw + row * DM + col)       = make_float2(acc[i][j][0], acc[i][j][1]);
            *(float2*)(Cw + (row + 8) * DM + col) = make_float2(acc[i][j][2], acc[i][j][3]);
        }
    }
}

// ---------------- scores = (Q_h @ K_h^T) / sqrt(hd), causal tile skip -------
__global__ __launch_bounds__(256, 2) void scores_kernel()
{
    const int bn = blockIdx.x, bm = blockIdx.y, z = blockIdx.z;
    if (bn > bm) return;
    const int b = z >> 4, h = z & 15;
    const float* Ab = g_q + ((size_t)(b * SEQ + bm * 128)) * DM + h * HD;
    const float* Bb = g_k + ((size_t)(b * SEQ + bn * 128)) * DM + h * HD;
    float*       Cb = g_p + (size_t)z * SEQ * SEQ + (size_t)(bm * 128) * SEQ + bn * 128;

    __shared__ __align__(16) float As[16][132];
    __shared__ __align__(16) float Bs[16][132];

    const int t  = threadIdx.x;
    const int tx = t & 15, ty = t >> 4;

    float acc[8][8];
#pragma unroll
    for (int i = 0; i < 8; i++)
#pragma unroll
        for (int j = 0; j < 8; j++) acc[i][j] = 0.f;

    for (int kt = 0; kt < HD; kt += 16) {
#pragma unroll
        for (int u = 0; u < 2; u++) {
            int idx = t + u * 256;
            int r   = idx >> 2;
            int k4  = (idx & 3) << 2;
            float4 av = *(const float4*)(Ab + (size_t)r * DM + kt + k4);
            As[k4 + 0][r] = av.x; As[k4 + 1][r] = av.y;
            As[k4 + 2][r] = av.z; As[k4 + 3][r] = av.w;
            float4 bv = *(const float4*)(Bb + (size_t)r * DM + kt + k4);
            Bs[k4 + 0][r] = bv.x; Bs[k4 + 1][r] = bv.y;
            Bs[k4 + 2][r] = bv.z; Bs[k4 + 3][r] = bv.w;
        }
        __syncthreads();
#pragma unroll
        for (int k = 0; k < 16; k++) {
            float4 a0 = *(const float4*)&As[k][ty * 8];
            float4 a1 = *(const float4*)&As[k][ty * 8 + 4];
            float4 b0 = *(const float4*)&Bs[k][tx * 8];
            float4 b1 = *(const float4*)&Bs[k][tx * 8 + 4];
            float a[8] = {a0.x, a0.y, a0.z, a0.w, a1.x, a1.y, a1.z, a1.w};
            float b[8] = {b0.x, b0.y, b0.z, b0.w, b1.x, b1.y, b1.z, b1.w};
#pragma unroll
            for (int i = 0; i < 8; i++)
#pragma unroll
                for (int j = 0; j < 8; j++)
                    acc[i][j] = fmaf(a[i], b[j], acc[i][j]);
        }
        __syncthreads();
    }

    const float scale = 0.088388347648318447f;
#pragma unroll
    for (int i = 0; i < 8; i++) {
        float* crow = Cb + (size_t)(ty * 8 + i) * SEQ + tx * 8;
        *(float4*)(crow)     = make_float4(acc[i][0] * scale, acc[i][1] * scale,
                                           acc[i][2] * scale, acc[i][3] * scale);
        *(float4*)(crow + 4) = make_float4(acc[i][4] * scale, acc[i][5] * scale,
                                           acc[i][6] * scale, acc[i][7] * scale);
    }
}

// ---------------- causal row softmax in place -------------------------------
__global__ __launch_bounds__(256) void softmax_kernel()
{
    const int q = blockIdx.x, z = blockIdx.y;
    float* row = g_p + (size_t)z * SEQ * SEQ + (size_t)q * SEQ;
    const int L = q + 1;
    __shared__ float red[256];
    const int tid = threadIdx.x;

    float m = -1e30f;
    for (int k = tid; k < L; k += 256) m = fmaxf(m, row[k]);
    red[tid] = m; __syncthreads();
    for (int s = 128; s > 0; s >>= 1) {
        if (tid < s) red[tid] = fmaxf(red[tid], red[tid + s]);
        __syncthreads();
    }
    const float rowmax = red[0];
    __syncthreads();

    float sum = 0.f;
    for (int k = tid; k < L; k += 256) {
        float e = __expf(row[k] - rowmax);
        row[k] = e;
        sum += e;
    }
    red[tid] = sum; __syncthreads();
    for (int s = 128; s > 0; s >>= 1) {
        if (tid < s) red[tid] += red[tid + s];
        __syncthreads();
    }
    const float inv = 1.0f / red[0];

    for (int k = tid; k < L; k += 256) row[k] *= inv;
    for (int k = L + tid; k < SEQ; k += 256) row[k] = 0.f;
}

// ---------------- O_h = P_h @ V_h (NN; causal K bound) ----------------------
__global__ __launch_bounds__(256, 2) void pv_kernel()
{
    const int bm = blockIdx.x, z = blockIdx.y;
    const int b = z >> 4, h = z & 15;
    const float* Ab    = g_p + (size_t)z * SEQ * SEQ + (size_t)(bm * 128) * SEQ;
    const float* Bbase = g_v + (size_t)(b * SEQ) * DM + h * HD;
    float*       Cb    = g_ao + (size_t)(b * SEQ + bm * 128) * DM + h * HD;
    const int Kdim = (bm + 1) * 128;

    __shared__ __align__(16) float As[16][132];
    __shared__ __align__(16) float Bs[16][132];

    const int t  = threadIdx.x;
    const int tx = t & 15, ty = t >> 4;

    float acc[8][8];
#pragma unroll
    for (int i = 0; i < 8; i++)
#pragma unroll
        for (int j = 0; j < 8; j++) acc[i][j] = 0.f;

    for (int kt = 0; kt < Kdim; kt += 16) {
#pragma unroll
        for (int u = 0; u < 2; u++) {
            int idx = t + u * 256;
            int r   = idx >> 2;
            int k4  = (idx & 3) << 2;
            float4 av = *(const float4*)(Ab + (size_t)r * SEQ + kt + k4);
            As[k4 + 0][r] = av.x; As[k4 + 1][r] = av.y;
            As[k4 + 2][r] = av.z; As[k4 + 3][r] = av.w;
            int rb = idx >> 5;
            int n4 = (idx & 31) << 2;
            float4 bv = *(const float4*)(Bbase + (size_t)(kt + rb) * DM + n4);
            *(float4*)&Bs[rb][n4] = bv;
        }
        __syncthreads();
#pragma unroll
        for (int k = 0; k < 16; k++) {
            float4 a0 = *(const float4*)&As[k][ty * 8];
            float4 a1 = *(const float4*)&As[k][ty * 8 + 4];
            float4 b0 = *(const float4*)&Bs[k][tx * 8];
            float4 b1 = *(const float4*)&Bs[k][tx * 8 + 4];
            float a[8] = {a0.x, a0.y, a0.z, a0.w, a1.x, a1.y, a1.z, a1.w};
            float b[8] = {b0.x, b0.y, b0.z, b0.w, b1.x, b1.y, b1.z, b1.w};
#pragma unroll
            for (int i = 0; i < 8; i++)
#pragma unroll
                for (int j = 0; j < 8; j++)
                    acc[i][j] = fmaf(a[i], b[j], acc[i][j]);
        }
        __syncthreads();
    }

#pragma unroll
    for (int i = 0; i < 8; i++) {
        float* crow = Cb + (size_t)(ty * 8 + i) * DM + tx * 8;
        *(float4*)(crow)     = make_float4(acc[i][0], acc[i][1], acc[i][2], acc[i][3]);
        *(float4*)(crow + 4) = make_float4(acc[i][4], acc[i][5], acc[i][6], acc[i][7]);
    }
}

// ---------------- launch ----------------------------------------------------
extern "C" void kernel_launch(void* const* d_in, const int* in_sizes, int n_in,
                              void* d_out, int out_size)
{
    const float* x  = (const float*)d_in[0];
    const float* Wq = (const float*)d_in[2];
    const float* Wk = (const float*)d_in[3];
    const float* Wv = (const float*)d_in[4];
    const float* Wo = (const float*)d_in[5];
    float* out = (float*)d_out;

    float *pq, *pk, *pvv, *pao;
    __nv_bfloat16 *pxs, *pws, *paos;
    cudaGetSymbolAddress((void**)&pq,   g_q);
    cudaGetSymbolAddress((void**)&pk,   g_k);
    cudaGetSymbolAddress((void**)&pvv,  g_v);
    cudaGetSymbolAddress((void**)&pao,  g_ao);
    cudaGetSymbolAddress((void**)&pxs,  g_xs);
    cudaGetSymbolAddress((void**)&pws,  g_ws);
    cudaGetSymbolAddress((void**)&paos, g_aos);

    rope_table_kernel<<<SEQ, HD / 2>>>();

    split_kernel<<<(MTOT * DM) / 256, 256>>>(x, pxs, MTOT * DM);
    split_kernel<<<(DM * DM) / 256, 256>>>(Wq, pws + 0ULL * DM * K3, DM * DM);
    split_kernel<<<(DM * DM) / 256, 256>>>(Wk, pws + 1ULL * DM * K3, DM * DM);
    split_kernel<<<(DM * DM) / 256, 256>>>(Wv, pws + 2ULL * DM * K3, DM * DM);
    split_kernel<<<(DM * DM) / 256, 256>>>(Wo, pws + 3ULL * DM * K3, DM * DM);

    mma_gemm_kernel<<<dim3(16, 32, 3), 256>>>(
        pxs, pws + 0ULL * DM * K3, pws + 1ULL * DM * K3, pws + 2ULL * DM * K3,
        pq, pk, pvv);

    rope_apply_kernel<<<(MTOT * (DM / 2)) / 256, 256>>>();
    scores_kernel<<<dim3(16, 16, 32), 256>>>();
    softmax_kernel<<<dim3(SEQ, 32), 256>>>();
    pv_kernel<<<dim3(16, 32), 256>>>();

    split_kernel<<<(MTOT * DM) / 256, 256>>>(pao, paos, MTOT * DM);
    mma_gemm_kernel<<<dim3(16, 32, 1), 256>>>(
        paos, pws + 3ULL * DM * K3, pws + 3ULL * DM * K3, pws + 3ULL * DM * K3,
        out, out, out);
}

// round 7
// speedup vs baseline: 2.0073x; 1.2513x over previous
#include <cuda_runtime.h>
#include <cuda_bf16.h>
#include <math.h>
#include <stdint.h>

#define SEQ    2048
#define DM     2048
#define NH     16
#define HD     128
#define NB     2
#define MTOT   (NB * SEQ)          // 4096
#define K3     4096                // split width: [hi(2048) | lo(2048)]
#define SA     40                  // smem row stride in bf16 (80B, conflict-free)
#define SB     136                 // smem row stride for [k][n] V tiles (272B)

// ---------------- scratch (device globals: allocation-free rule) ------------
static __device__ float g_q [(size_t)MTOT * DM];            // 32 MB
static __device__ float g_k [(size_t)MTOT * DM];            // 32 MB
static __device__ float g_v [(size_t)MTOT * DM];            // 32 MB
static __device__ float g_ao[(size_t)MTOT * DM];            // 32 MB
static __device__ float g_p [2ULL * NH * SEQ * SEQ];        // 512 MB scores
static __device__ float g_cos[SEQ * (HD / 2)];
static __device__ float g_sin[SEQ * (HD / 2)];
static __device__ __nv_bfloat16 g_xs [(size_t)MTOT * K3];   // x split (K3 layout)
static __device__ __nv_bfloat16 g_ws [4ULL * DM * K3];      // W splits (K3 layout)
static __device__ __nv_bfloat16 g_aos[(size_t)MTOT * K3];   // attn-out split
static __device__ __nv_bfloat16 g_qhi[(size_t)MTOT * DM];   // roped q hi
static __device__ __nv_bfloat16 g_qlo[(size_t)MTOT * DM];   // roped q lo
static __device__ __nv_bfloat16 g_khi[(size_t)MTOT * DM];
static __device__ __nv_bfloat16 g_klo[(size_t)MTOT * DM];
static __device__ __nv_bfloat16 g_vhi[(size_t)MTOT * DM];
static __device__ __nv_bfloat16 g_vlo[(size_t)MTOT * DM];
static __device__ __nv_bfloat16 g_phi[2ULL * NH * SEQ * SEQ];  // 256 MB
static __device__ __nv_bfloat16 g_plo[2ULL * NH * SEQ * SEQ];  // 256 MB

// ---------------- PTX helpers (all baseline ISA, no 'a' features) -----------
__device__ __forceinline__ uint32_t smem_u32(const void* p) {
    uint32_t a;
    asm("{ .reg .u64 t; cvta.to.shared.u64 t, %1; cvt.u32.u64 %0, t; }"
        : "=r"(a) : "l"(p));
    return a;
}

__device__ __forceinline__ void cp16(uint32_t saddr, const void* g) {
    asm volatile("cp.async.cg.shared.global [%0], [%1], 16;"
                 :: "r"(saddr), "l"(g));
}

__device__ __forceinline__ void ldm_x4(uint32_t addr, uint32_t& r0, uint32_t& r1,
                                       uint32_t& r2, uint32_t& r3) {
    asm volatile("ldmatrix.sync.aligned.m8n8.x4.shared.b16 {%0,%1,%2,%3}, [%4];"
                 : "=r"(r0), "=r"(r1), "=r"(r2), "=r"(r3) : "r"(addr));
}

__device__ __forceinline__ void ldm_x4t(uint32_t addr, uint32_t& r0, uint32_t& r1,
                                        uint32_t& r2, uint32_t& r3) {
    asm volatile("ldmatrix.sync.aligned.m8n8.x4.trans.shared.b16 {%0,%1,%2,%3}, [%4];"
                 : "=r"(r0), "=r"(r1), "=r"(r2), "=r"(r3) : "r"(addr));
}

__device__ __forceinline__ void mma_bf16(float* c, const uint32_t* a, const uint32_t* b) {
    asm volatile(
        "mma.sync.aligned.m16n8k16.row.col.f32.bf16.bf16.f32 "
        "{%0,%1,%2,%3}, {%4,%5,%6,%7}, {%8,%9}, {%0,%1,%2,%3};"
        : "+f"(c[0]), "+f"(c[1]), "+f"(c[2]), "+f"(c[3])
        : "r"(a[0]), "r"(a[1]), "r"(a[2]), "r"(a[3]), "r"(b[0]), "r"(b[1]));
}

// ---------------- RoPE table (match jnp: fp32 angle, accurate trig) ---------
__global__ void rope_table_kernel()
{
    int s = blockIdx.x;          // 0..2047
    int i = threadIdx.x;         // 0..63
    double e    = ((double)(2 * i)) / (double)HD;
    double powd = pow(10000.0, e);
    float  invf = (float)(1.0 / powd);
    float  fr   = (float)s * invf;
    double a    = (double)fr;
    g_cos[s * (HD / 2) + i] = (float)cos(a);
    g_sin[s * (HD / 2) + i] = (float)sin(a);
}

// RoPE apply fused with hi/lo bf16 split: reads fp32 q/k, writes 4 split arrays.
__global__ __launch_bounds__(256) void rope_apply_kernel()
{
    size_t idx = (size_t)blockIdx.x * 256 + threadIdx.x;
    int    i   = (int)(idx & 63);
    size_t cp  = idx & 1023;
    size_t m   = idx >> 10;
    int    s   = (int)(m & (SEQ - 1));
    float  c   = g_cos[s * (HD / 2) + i];
    float  sn  = g_sin[s * (HD / 2) + i];
    size_t off = m * (DM / 2) + cp;

    float2 qv = ((const float2*)g_q)[off];
    float qx = qv.x * c - qv.y * sn;
    float qy = qv.x * sn + qv.y * c;
    float2 kv = ((const float2*)g_k)[off];
    float kx = kv.x * c - kv.y * sn;
    float ky = kv.x * sn + kv.y * c;

    __nv_bfloat162 h2, l2;
    h2.x = __float2bfloat16(qx); l2.x = __float2bfloat16(qx - __bfloat162float(h2.x));
    h2.y = __float2bfloat16(qy); l2.y = __float2bfloat16(qy - __bfloat162float(h2.y));
    ((__nv_bfloat162*)g_qhi)[off] = h2;
    ((__nv_bfloat162*)g_qlo)[off] = l2;

    h2.x = __float2bfloat16(kx); l2.x = __float2bfloat16(kx - __bfloat162float(h2.x));
    h2.y = __float2bfloat16(ky); l2.y = __float2bfloat16(ky - __bfloat162float(h2.y));
    ((__nv_bfloat162*)g_khi)[off] = h2;
    ((__nv_bfloat162*)g_klo)[off] = l2;
}

// ---------------- bf16 hi/lo split: K3-interleaved layout (for projections) --
__global__ __launch_bounds__(256) void split_kernel(const float* __restrict__ src,
                                                    __nv_bfloat16* __restrict__ dst,
                                                    int n)
{
    int i = blockIdx.x * 256 + threadIdx.x;
    if (i >= n) return;
    size_t r  = (size_t)(i >> 11);
    int    cc = i & 2047;
    float v = src[i];
    __nv_bfloat16 hi = __float2bfloat16(v);            // RN
    float hv = __bfloat162float(hi);
    __nv_bfloat16 lo = __float2bfloat16(v - hv);
    dst[r * K3 + cc]        = hi;
    dst[r * K3 + 2048 + cc] = lo;
}

// ---------------- plain hi/lo split (same indexing) for V -------------------
__global__ __launch_bounds__(256) void splitv_kernel()
{
    int i = blockIdx.x * 256 + threadIdx.x;
    float v = g_v[i];
    __nv_bfloat16 hi = __float2bfloat16(v);
    g_vhi[i] = hi;
    g_vlo[i] = __float2bfloat16(v - __bfloat162float(hi));
}

// ---------------- mma.sync bf16x3 GEMM: C[m,n] = sum_k A[m,k] B[n,k] --------
__global__ void __launch_bounds__(256) mma_gemm_kernel(
    const __nv_bfloat16* __restrict__ A,
    const __nv_bfloat16* __restrict__ B0, const __nv_bfloat16* __restrict__ B1,
    const __nv_bfloat16* __restrict__ B2,
    float* __restrict__ C0, float* __restrict__ C1, float* __restrict__ C2)
{
    const __nv_bfloat16* Bw = (blockIdx.z == 0) ? B0 : (blockIdx.z == 1) ? B1 : B2;
    float*               Cw = (blockIdx.z == 0) ? C0 : (blockIdx.z == 1) ? C1 : C2;

    __shared__ __align__(16) __nv_bfloat16 sm_a[2][128 * SA];
    __shared__ __align__(16) __nv_bfloat16 sm_b[2][128 * SA];

    const int t    = threadIdx.x;
    const int wid  = t >> 5;
    const int lane = t & 31;
    const int wm0  = (wid >> 2) * 64;
    const int wn0  = (wid & 3) * 32;

    const size_t m0 = (size_t)blockIdx.y * 128;
    const size_t n0 = (size_t)blockIdx.x * 128;
    const __nv_bfloat16* Ab = A  + m0 * K3;
    const __nv_bfloat16* Bb = Bw + n0 * K3;

    const uint32_t sa0 = smem_u32(&sm_a[0][0]);
    const uint32_t sa1 = smem_u32(&sm_a[1][0]);
    const uint32_t sb0 = smem_u32(&sm_b[0][0]);
    const uint32_t sb1 = smem_u32(&sm_b[1][0]);

    const int lr0 = t >> 2, ls0 = t & 3;
    const int lr1 = lr0 + 64, ls1 = ls0;

    float acc[4][4][4];
#pragma unroll
    for (int i = 0; i < 4; i++)
#pragma unroll
        for (int j = 0; j < 4; j++)
#pragma unroll
            for (int r = 0; r < 4; r++) acc[i][j][r] = 0.f;

    const int atile = lane >> 3;
    const int arow8 = (atile & 1) * 8;
    const int akof  = (atile >> 1) * 8;
    const int bnof  = (atile >> 1) * 8;
    const int bkof  = (atile & 1) * 8;
    const int l8    = lane & 7;

    const int NC = 192;
    {
        cp16(sa0 + (lr0 * SA + ls0 * 8) * 2, Ab + (size_t)lr0 * K3 + ls0 * 8);
        cp16(sb0 + (lr0 * SA + ls0 * 8) * 2, Bb + (size_t)lr0 * K3 + ls0 * 8);
        cp16(sa0 + (lr1 * SA + ls1 * 8) * 2, Ab + (size_t)lr1 * K3 + ls1 * 8);
        cp16(sb0 + (lr1 * SA + ls1 * 8) * 2, Bb + (size_t)lr1 * K3 + ls1 * 8);
        asm volatile("cp.async.commit_group;" ::: "memory");
    }

    for (int c = 0; c < NC; ++c) {
        const int buf = c & 1;
        const int cn  = c + 1;
        if (cn < NC) {
            const int nbuf = cn & 1;
            const uint32_t na = nbuf ? sa1 : sa0;
            const uint32_t nb = nbuf ? sb1 : sb0;
            const int seg = cn >> 6;
            const int kin = (cn & 63) << 5;
            const int kA  = ((seg == 2) ? 2048 : 0) + kin;
            const int kB  = ((seg == 1) ? 2048 : 0) + kin;
            cp16(na + (lr0 * SA + ls0 * 8) * 2, Ab + (size_t)lr0 * K3 + kA + ls0 * 8);
            cp16(nb + (lr0 * SA + ls0 * 8) * 2, Bb + (size_t)lr0 * K3 + kB + ls0 * 8);
            cp16(na + (lr1 * SA + ls1 * 8) * 2, Ab + (size_t)lr1 * K3 + kA + ls1 * 8);
            cp16(nb + (lr1 * SA + ls1 * 8) * 2, Bb + (size_t)lr1 * K3 + kB + ls1 * 8);
            asm volatile("cp.async.commit_group;" ::: "memory");
            asm volatile("cp.async.wait_group 1;" ::: "memory");
        } else {
            asm volatile("cp.async.wait_group 0;" ::: "memory");
        }
        __syncthreads();

        const uint32_t ab = buf ? sa1 : sa0;
        const uint32_t bb = buf ? sb1 : sb0;

#pragma unroll
        for (int kk = 0; kk < 32; kk += 16) {
            uint32_t af[4][4], bf[4][2];
#pragma unroll
            for (int i = 0; i < 4; ++i) {
                int row = wm0 + 16 * i + arow8 + l8;
                ldm_x4(ab + (uint32_t)(row * SA + kk + akof) * 2,
                       af[i][0], af[i][1], af[i][2], af[i][3]);
            }
#pragma unroll
            for (int jp = 0; jp < 2; ++jp) {
                int n = wn0 + 16 * jp + bnof + l8;
                uint32_t r0, r1, r2, r3;
                ldm_x4(bb + (uint32_t)(n * SA + kk + bkof) * 2, r0, r1, r2, r3);
                bf[2 * jp + 0][0] = r0; bf[2 * jp + 0][1] = r1;
                bf[2 * jp + 1][0] = r2; bf[2 * jp + 1][1] = r3;
            }
#pragma unroll
            for (int i = 0; i < 4; ++i)
#pragma unroll
                for (int j = 0; j < 4; ++j)
                    mma_bf16(acc[i][j], af[i], bf[j]);
        }
        __syncthreads();
    }

    const int rbase = lane >> 2;
    const int cbase = (lane & 3) * 2;
#pragma unroll
    for (int i = 0; i < 4; ++i) {
#pragma unroll
        for (int j = 0; j < 4; ++j) {
            size_t row = m0 + wm0 + 16 * i + rbase;
            size_t col = n0 + wn0 + 8 * j + cbase;
            *(float2*)(Cw + row * DM + col)       = make_float2(acc[i][j][0], acc[i][j][1]);
            *(float2*)(Cw + (row + 8) * DM + col) = make_float2(acc[i][j][2], acc[i][j][3]);
        }
    }
}

// ---------------- scores via mma: S = (Q K^T)/sqrt(hd), bf16x3 split --------
// grid (16 bn, 16 bm, 32 bh); NT GEMM, K_eff = 3 x 128.
__global__ void __launch_bounds__(256, 2) scores_mma_kernel()
{
    const int bn = blockIdx.x, bm = blockIdx.y, z = blockIdx.z;
    if (bn > bm) return;
    const int b = z >> 4, h = z & 15;

    __shared__ __align__(16) __nv_bfloat16 sm_a[2][128 * SA];
    __shared__ __align__(16) __nv_bfloat16 sm_b[2][128 * SA];

    const int t    = threadIdx.x;
    const int wid  = t >> 5;
    const int lane = t & 31;
    const int wm0  = (wid >> 2) * 64;
    const int wn0  = (wid & 3) * 32;

    const size_t arow = (size_t)(b * SEQ + bm * 128);
    const size_t brow = (size_t)(b * SEQ + bn * 128);
    const __nv_bfloat16* Aqh = g_qhi + arow * DM + h * HD;
    const __nv_bfloat16* Aql = g_qlo + arow * DM + h * HD;
    const __nv_bfloat16* Bkh = g_khi + brow * DM + h * HD;
    const __nv_bfloat16* Bkl = g_klo + brow * DM + h * HD;
    float* Cb = g_p + (size_t)z * SEQ * SEQ + (size_t)(bm * 128) * SEQ + bn * 128;

    const uint32_t sa0 = smem_u32(&sm_a[0][0]);
    const uint32_t sa1 = smem_u32(&sm_a[1][0]);
    const uint32_t sb0 = smem_u32(&sm_b[0][0]);
    const uint32_t sb1 = smem_u32(&sm_b[1][0]);

    const int lr0 = t >> 2, ls0 = t & 3;
    const int lr1 = lr0 + 64;

    float acc[4][4][4];
#pragma unroll
    for (int i = 0; i < 4; i++)
#pragma unroll
        for (int j = 0; j < 4; j++)
#pragma unroll
            for (int r = 0; r < 4; r++) acc[i][j][r] = 0.f;

    const int atile = lane >> 3;
    const int arow8 = (atile & 1) * 8;
    const int akof  = (atile >> 1) * 8;
    const int bnof  = (atile >> 1) * 8;
    const int bkof  = (atile & 1) * 8;
    const int l8    = lane & 7;

    const int NC = 12;          // 3 segs x 4 chunks of K=32
    {
        cp16(sa0 + (lr0 * SA + ls0 * 8) * 2, Aqh + (size_t)lr0 * DM + ls0 * 8);
        cp16(sb0 + (lr0 * SA + ls0 * 8) * 2, Bkh + (size_t)lr0 * DM + ls0 * 8);
        cp16(sa0 + (lr1 * SA + ls0 * 8) * 2, Aqh + (size_t)lr1 * DM + ls0 * 8);
        cp16(sb0 + (lr1 * SA + ls0 * 8) * 2, Bkh + (size_t)lr1 * DM + ls0 * 8);
        asm volatile("cp.async.commit_group;" ::: "memory");
    }

    for (int c = 0; c < NC; ++c) {
        const int buf = c & 1;
        const int cn  = c + 1;
        if (cn < NC) {
            const int nbuf = cn & 1;
            const uint32_t na = nbuf ? sa1 : sa0;
            const uint32_t nb = nbuf ? sb1 : sb0;
            const int seg = cn >> 2;
            const int kin = (cn & 3) << 5;
            const __nv_bfloat16* As = (seg == 2) ? Aql : Aqh;
            const __nv_bfloat16* Bs = (seg == 1) ? Bkl : Bkh;
            cp16(na + (lr0 * SA + ls0 * 8) * 2, As + (size_t)lr0 * DM + kin + ls0 * 8);
            cp16(nb + (lr0 * SA + ls0 * 8) * 2, Bs + (size_t)lr0 * DM + kin + ls0 * 8);
            cp16(na + (lr1 * SA + ls0 * 8) * 2, As + (size_t)lr1 * DM + kin + ls0 * 8);
            cp16(nb + (lr1 * SA + ls0 * 8) * 2, Bs + (size_t)lr1 * DM + kin + ls0 * 8);
            asm volatile("cp.async.commit_group;" ::: "memory");
            asm volatile("cp.async.wait_group 1;" ::: "memory");
        } else {
            asm volatile("cp.async.wait_group 0;" ::: "memory");
        }
        __syncthreads();

        const uint32_t ab = buf ? sa1 : sa0;
        const uint32_t bb = buf ? sb1 : sb0;

#pragma unroll
        for (int kk = 0; kk < 32; kk += 16) {
            uint32_t af[4][4], bf[4][2];
#pragma unroll
            for (int i = 0; i < 4; ++i) {
                int row = wm0 + 16 * i + arow8 + l8;
                ldm_x4(ab + (uint32_t)(row * SA + kk + akof) * 2,
                       af[i][0], af[i][1], af[i][2], af[i][3]);
            }
#pragma unroll
            for (int jp = 0; jp < 2; ++jp) {
                int n = wn0 + 16 * jp + bnof + l8;
                uint32_t r0, r1, r2, r3;
                ldm_x4(bb + (uint32_t)(n * SA + kk + bkof) * 2, r0, r1, r2, r3);
                bf[2 * jp + 0][0] = r0; bf[2 * jp + 0][1] = r1;
                bf[2 * jp + 1][0] = r2; bf[2 * jp + 1][1] = r3;
            }
#pragma unroll
            for (int i = 0; i < 4; ++i)
#pragma unroll
                for (int j = 0; j < 4; ++j)
                    mma_bf16(acc[i][j], af[i], bf[j]);
        }
        __syncthreads();
    }

    const float scale = 0.088388347648318447f;   // 1/sqrt(128)
    const int rbase = lane >> 2;
    const int cbase = (lane & 3) * 2;
#pragma unroll
    for (int i = 0; i < 4; ++i) {
#pragma unroll
        for (int j = 0; j < 4; ++j) {
            int row = wm0 + 16 * i + rbase;
            int col = wn0 + 8 * j + cbase;
            *(float2*)(Cb + (size_t)row * SEQ + col) =
                make_float2(acc[i][j][0] * scale, acc[i][j][1] * scale);
            *(float2*)(Cb + (size_t)(row + 8) * SEQ + col) =
                make_float2(acc[i][j][2] * scale, acc[i][j][3] * scale);
        }
    }
}

// ---------------- causal row softmax: fp32 scores -> bf16 hi/lo probs -------
__global__ __launch_bounds__(256) void softmax_kernel()
{
    const int q = blockIdx.x, z = blockIdx.y;
    const size_t rb = (size_t)z * SEQ * SEQ + (size_t)q * SEQ;
    const float* row = g_p + rb;
    __nv_bfloat16* ph = g_phi + rb;
    __nv_bfloat16* pl = g_plo + rb;
    const int L  = q + 1;
    const int Lz = ((q >> 7) + 1) << 7;   // pv reads only k < Lz
    __shared__ float red[256];
    const int tid = threadIdx.x;

    float m = -1e30f;
    for (int k = tid; k < L; k += 256) m = fmaxf(m, row[k]);
    red[tid] = m; __syncthreads();
    for (int s = 128; s > 0; s >>= 1) {
        if (tid < s) red[tid] = fmaxf(red[tid], red[tid + s]);
        __syncthreads();
    }
    const float rowmax = red[0];
    __syncthreads();

    float sum = 0.f;
    for (int k = tid; k < L; k += 256) sum += __expf(row[k] - rowmax);
    red[tid] = sum; __syncthreads();
    for (int s = 128; s > 0; s >>= 1) {
        if (tid < s) red[tid] += red[tid + s];
        __syncthreads();
    }
    const float inv = 1.0f / red[0];

    for (int k = tid; k < L; k += 256) {
        float p = __expf(row[k] - rowmax) * inv;
        __nv_bfloat16 hi = __float2bfloat16(p);
        ph[k] = hi;
        pl[k] = __float2bfloat16(p - __bfloat162float(hi));
    }
    const __nv_bfloat16 zz = __float2bfloat16(0.f);
    for (int k = L + tid; k < Lz; k += 256) { ph[k] = zz; pl[k] = zz; }
}

// ---------------- O = P V via mma, bf16x3 split, causal K bound -------------
// grid (16 bm, 32 bh). A = P [128 x K] (row stride SEQ), B = V [K x 128]
// loaded natural [k][n] and fragmented via ldmatrix.trans.
__global__ void __launch_bounds__(256, 2) pv_mma_kernel()
{
    const int bm = blockIdx.x, z = blockIdx.y;
    const int b = z >> 4, h = z & 15;

    __shared__ __align__(16) __nv_bfloat16 sm_a[2][128 * SA];
    __shared__ __align__(16) __nv_bfloat16 sm_b[2][32 * SB];

    const int t    = threadIdx.x;
    const int wid  = t >> 5;
    const int lane = t & 31;
    const int wm0  = (wid >> 2) * 64;
    const int wn0  = (wid & 3) * 32;

    const size_t pbase = (size_t)z * SEQ * SEQ + (size_t)(bm * 128) * SEQ;
    const __nv_bfloat16* Aph = g_phi + pbase;
    const __nv_bfloat16* Apl = g_plo + pbase;
    const __nv_bfloat16* Bvh = g_vhi + (size_t)(b * SEQ) * DM + h * HD;
    const __nv_bfloat16* Bvl = g_vlo + (size_t)(b * SEQ) * DM + h * HD;
    float* Cb = g_ao + (size_t)(b * SEQ + bm * 128) * DM + h * HD;

    const uint32_t sa0 = smem_u32(&sm_a[0][0]);
    const uint32_t sa1 = smem_u32(&sm_a[1][0]);
    const uint32_t sb0 = smem_u32(&sm_b[0][0]);
    const uint32_t sb1 = smem_u32(&sm_b[1][0]);

    // A slots: 512 = 128 rows x 4 x16B ; B slots: 512 = 32 rows x 16 x16B
    const int alr0 = t >> 2, als0 = t & 3;
    const int alr1 = alr0 + 64;
    const int blr0 = t >> 4, bls0 = t & 15;   // rows 0..15
    const int blr1 = blr0 + 16, bls1 = bls0;  // rows 16..31

    float acc[4][4][4];
#pragma unroll
    for (int i = 0; i < 4; i++)
#pragma unroll
        for (int j = 0; j < 4; j++)
#pragma unroll
            for (int r = 0; r < 4; r++) acc[i][j][r] = 0.f;

    const int atile = lane >> 3;
    const int arow8 = (atile & 1) * 8;
    const int akof  = (atile >> 1) * 8;
    const int bkof  = (atile & 1) * 8;       // trans: k offset within 16
    const int bnof  = (atile >> 1) * 8;      // trans: n offset within 16
    const int l8    = lane & 7;

    const int npc = (bm + 1) * 4;            // K chunks per segment
    const int NC  = 3 * npc;
    {
        cp16(sa0 + (alr0 * SA + als0 * 8) * 2, Aph + (size_t)alr0 * SEQ + als0 * 8);
        cp16(sa0 + (alr1 * SA + als0 * 8) * 2, Aph + (size_t)alr1 * SEQ + als0 * 8);
        cp16(sb0 + (blr0 * SB + bls0 * 8) * 2, Bvh + (size_t)blr0 * DM + bls0 * 8);
        cp16(sb0 + (blr1 * SB + bls1 * 8) * 2, Bvh + (size_t)blr1 * DM + bls1 * 8);
        asm volatile("cp.async.commit_group;" ::: "memory");
    }

    for (int c = 0; c < NC; ++c) {
        const int buf = c & 1;
        const int cn  = c + 1;
        if (cn < NC) {
            const int nbuf = cn & 1;
            const uint32_t na = nbuf ? sa1 : sa0;
            const uint32_t nb = nbuf ? sb1 : sb0;
            const int seg = (cn >= 2 * npc) ? 2 : ((cn >= npc) ? 1 : 0);
            const int kin = (cn - seg * npc) << 5;
            const __nv_bfloat16* As = (seg == 2) ? Apl : Aph;
            const __nv_bfloat16* Bs = (seg == 1) ? Bvl : Bvh;
            cp16(na + (alr0 * SA + als0 * 8) * 2, As + (size_t)alr0 * SEQ + kin + als0 * 8);
            cp16(na + (alr1 * SA + als0 * 8) * 2, As + (size_t)alr1 * SEQ + kin + als0 * 8);
            cp16(nb + (blr0 * SB + bls0 * 8) * 2, Bs + (size_t)(kin + blr0) * DM + bls0 * 8);
            cp16(nb + (blr1 * SB + bls1 * 8) * 2, Bs + (size_t)(kin + blr1) * DM + bls1 * 8);
            asm volatile("cp.async.commit_group;" ::: "memory");
            asm volatile("cp.async.wait_group 1;" ::: "memory");
        } else {
            asm volatile("cp.async.wait_group 0;" ::: "memory");
        }
        __syncthreads();

        const uint32_t ab = buf ? sa1 : sa0;
        const uint32_t bb = buf ? sb1 : sb0;

#pragma unroll
        for (int kk = 0; kk < 32; kk += 16) {
            uint32_t af[4][4], bf[4][2];
#pragma unroll
            for (int i = 0; i < 4; ++i) {
                int row = wm0 + 16 * i + arow8 + l8;
                ldm_x4(ab + (uint32_t)(row * SA + kk + akof) * 2,
                       af[i][0], af[i][1], af[i][2], af[i][3]);
            }
#pragma unroll
            for (int jp = 0; jp < 2; ++jp) {
                // source tile rows = k, cols = n ; .trans gives col-major frags
                int srow = kk + bkof + l8;
                int scol = wn0 + 16 * jp + bnof;
                uint32_t r0, r1, r2, r3;
                ldm_x4t(bb + (uint32_t)(srow * SB + scol) * 2, r0, r1, r2, r3);
                bf[2 * jp + 0][0] = r0; bf[2 * jp + 0][1] = r1;
                bf[2 * jp + 1][0] = r2; bf[2 * jp + 1][1] = r3;
            }
#pragma unroll
            for (int i = 0; i < 4; ++i)
#pragma unroll
                for (int j = 0; j < 4; ++j)
                    mma_bf16(acc[i][j], af[i], bf[j]);
        }
        __syncthreads();
    }

    const int rbase = lane >> 2;
    const int cbase = (lane & 3) * 2;
#pragma unroll
    for (int i = 0; i < 4; ++i) {
#pragma unroll
        for (int j = 0; j < 4; ++j) {
            int row = wm0 + 16 * i + rbase;
            int col = wn0 + 8 * j + cbase;
            *(float2*)(Cb + (size_t)row * DM + col) =
                make_float2(acc[i][j][0], acc[i][j][1]);
            *(float2*)(Cb + (size_t)(row + 8) * DM + col) =
                make_float2(acc[i][j][2], acc[i][j][3]);
        }
    }
}

// ---------------- launch ----------------------------------------------------
extern "C" void kernel_launch(void* const* d_in, const int* in_sizes, int n_in,
                              void* d_out, int out_size)
{
    const float* x  = (const float*)d_in[0];
    const float* Wq = (const float*)d_in[2];
    const float* Wk = (const float*)d_in[3];
    const float* Wv = (const float*)d_in[4];
    const float* Wo = (const float*)d_in[5];
    float* out = (float*)d_out;

    float *pq, *pk, *pvv, *pao;
    __nv_bfloat16 *pxs, *pws, *paos;
    cudaGetSymbolAddress((void**)&pq,   g_q);
    cudaGetSymbolAddress((void**)&pk,   g_k);
    cudaGetSymbolAddress((void**)&pvv,  g_v);
    cudaGetSymbolAddress((void**)&pao,  g_ao);
    cudaGetSymbolAddress((void**)&pxs,  g_xs);
    cudaGetSymbolAddress((void**)&pws,  g_ws);
    cudaGetSymbolAddress((void**)&paos, g_aos);

    rope_table_kernel<<<SEQ, HD / 2>>>();

    split_kernel<<<(MTOT * DM) / 256, 256>>>(x, pxs, MTOT * DM);
    split_kernel<<<(DM * DM) / 256, 256>>>(Wq, pws + 0ULL * DM * K3, DM * DM);
    split_kernel<<<(DM * DM) / 256, 256>>>(Wk, pws + 1ULL * DM * K3, DM * DM);
    split_kernel<<<(DM * DM) / 256, 256>>>(Wv, pws + 2ULL * DM * K3, DM * DM);
    split_kernel<<<(DM * DM) / 256, 256>>>(Wo, pws + 3ULL * DM * K3, DM * DM);

    mma_gemm_kernel<<<dim3(16, 32, 3), 256>>>(
        pxs, pws + 0ULL * DM * K3, pws + 1ULL * DM * K3, pws + 2ULL * DM * K3,
        pq, pk, pvv);

    rope_apply_kernel<<<(MTOT * (DM / 2)) / 256, 256>>>();
    splitv_kernel<<<(MTOT * DM) / 256, 256>>>();

    scores_mma_kernel<<<dim3(16, 16, 32), 256>>>();
    softmax_kernel<<<dim3(SEQ, 32), 256>>>();
    pv_mma_kernel<<<dim3(16, 32), 256>>>();

    split_kernel<<<(MTOT * DM) / 256, 256>>>(pao, paos, MTOT * DM);
    mma_gemm_kernel<<<dim3(16, 32, 1), 256>>>(
        paos, pws + 3ULL * DM * K3, pws + 3ULL * DM * K3, pws + 3ULL * DM * K3,
        out, out, out);
}

// round 8
// speedup vs baseline: 2.0469x; 1.0197x over previous
#include <cuda_runtime.h>
#include <cuda_bf16.h>
#include <math.h>
#include <stdint.h>

#define SEQ    2048
#define DM     2048
#define NH     16
#define HD     128
#define NB     2
#define MTOT   (NB * SEQ)          // 4096
#define K3     4096                // split width: [hi(2048) | lo(2048)]
#define SA     40                  // smem row stride (scores/pv kernels)
#define SB     136                 // smem row stride for [k][n] V tiles
#define SAW    72                  // smem row stride for K=64 chunks (144B)

// gemm2 smem layout (dynamic)
#define A_STAGE (256 * SAW * 2)    // 36864 B
#define B_STAGE (128 * SAW * 2)    // 18432 B
#define B_OFF   (3 * A_STAGE)      // 110592
#define GEMM2_SMEM (3 * A_STAGE + 3 * B_STAGE)   // 165888 B

// ---------------- scratch (device globals: allocation-free rule) ------------
static __device__ float g_q [(size_t)MTOT * DM];            // 32 MB
static __device__ float g_k [(size_t)MTOT * DM];            // 32 MB
static __device__ float g_p [2ULL * NH * SEQ * SEQ];        // 512 MB scores
static __device__ float g_cos[SEQ * (HD / 2)];
static __device__ float g_sin[SEQ * (HD / 2)];
static __device__ __nv_bfloat16 g_xs [(size_t)MTOT * K3];   // x split (K3 layout)
static __device__ __nv_bfloat16 g_ws [4ULL * DM * K3];      // W splits (K3 layout)
static __device__ __nv_bfloat16 g_aos[(size_t)MTOT * K3];   // attn-out split (K3)
static __device__ __nv_bfloat16 g_qhi[(size_t)MTOT * DM];
static __device__ __nv_bfloat16 g_qlo[(size_t)MTOT * DM];
static __device__ __nv_bfloat16 g_khi[(size_t)MTOT * DM];
static __device__ __nv_bfloat16 g_klo[(size_t)MTOT * DM];
static __device__ __nv_bfloat16 g_vhi[(size_t)MTOT * DM];
static __device__ __nv_bfloat16 g_vlo[(size_t)MTOT * DM];
static __device__ __nv_bfloat16 g_phi[2ULL * NH * SEQ * SEQ];  // 256 MB
static __device__ __nv_bfloat16 g_plo[2ULL * NH * SEQ * SEQ];  // 256 MB

// ---------------- PTX helpers (baseline ISA only) ---------------------------
__device__ __forceinline__ uint32_t smem_u32(const void* p) {
    uint32_t a;
    asm("{ .reg .u64 t; cvta.to.shared.u64 t, %1; cvt.u32.u64 %0, t; }"
        : "=r"(a) : "l"(p));
    return a;
}

__device__ __forceinline__ void cp16(uint32_t saddr, const void* g) {
    asm volatile("cp.async.cg.shared.global [%0], [%1], 16;"
                 :: "r"(saddr), "l"(g));
}

__device__ __forceinline__ void ldm_x4(uint32_t addr, uint32_t& r0, uint32_t& r1,
                                       uint32_t& r2, uint32_t& r3) {
    asm volatile("ldmatrix.sync.aligned.m8n8.x4.shared.b16 {%0,%1,%2,%3}, [%4];"
                 : "=r"(r0), "=r"(r1), "=r"(r2), "=r"(r3) : "r"(addr));
}

__device__ __forceinline__ void ldm_x4t(uint32_t addr, uint32_t& r0, uint32_t& r1,
                                        uint32_t& r2, uint32_t& r3) {
    asm volatile("ldmatrix.sync.aligned.m8n8.x4.trans.shared.b16 {%0,%1,%2,%3}, [%4];"
                 : "=r"(r0), "=r"(r1), "=r"(r2), "=r"(r3) : "r"(addr));
}

__device__ __forceinline__ void mma_bf16(float* c, const uint32_t* a, const uint32_t* b) {
    asm volatile(
        "mma.sync.aligned.m16n8k16.row.col.f32.bf16.bf16.f32 "
        "{%0,%1,%2,%3}, {%4,%5,%6,%7}, {%8,%9}, {%0,%1,%2,%3};"
        : "+f"(c[0]), "+f"(c[1]), "+f"(c[2]), "+f"(c[3])
        : "r"(a[0]), "r"(a[1]), "r"(a[2]), "r"(a[3]), "r"(b[0]), "r"(b[1]));
}

// ---------------- RoPE table (match jnp: fp32 angle, accurate trig) ---------
__global__ void rope_table_kernel()
{
    int s = blockIdx.x;
    int i = threadIdx.x;
    double e    = ((double)(2 * i)) / (double)HD;
    double powd = pow(10000.0, e);
    float  invf = (float)(1.0 / powd);
    float  fr   = (float)s * invf;
    double a    = (double)fr;
    g_cos[s * (HD / 2) + i] = (float)cos(a);
    g_sin[s * (HD / 2) + i] = (float)sin(a);
}

// RoPE apply fused with hi/lo bf16 split.
__global__ __launch_bounds__(256) void rope_apply_kernel()
{
    size_t idx = (size_t)blockIdx.x * 256 + threadIdx.x;
    int    i   = (int)(idx & 63);
    size_t cp  = idx & 1023;
    size_t m   = idx >> 10;
    int    s   = (int)(m & (SEQ - 1));
    float  c   = g_cos[s * (HD / 2) + i];
    float  sn  = g_sin[s * (HD / 2) + i];
    size_t off = m * (DM / 2) + cp;

    float2 qv = ((const float2*)g_q)[off];
    float qx = qv.x * c - qv.y * sn;
    float qy = qv.x * sn + qv.y * c;
    float2 kv = ((const float2*)g_k)[off];
    float kx = kv.x * c - kv.y * sn;
    float ky = kv.x * sn + kv.y * c;

    __nv_bfloat162 h2, l2;
    h2.x = __float2bfloat16(qx); l2.x = __float2bfloat16(qx - __bfloat162float(h2.x));
    h2.y = __float2bfloat16(qy); l2.y = __float2bfloat16(qy - __bfloat162float(h2.y));
    ((__nv_bfloat162*)g_qhi)[off] = h2;
    ((__nv_bfloat162*)g_qlo)[off] = l2;

    h2.x = __float2bfloat16(kx); l2.x = __float2bfloat16(kx - __bfloat162float(h2.x));
    h2.y = __float2bfloat16(ky); l2.y = __float2bfloat16(ky - __bfloat162float(h2.y));
    ((__nv_bfloat162*)g_khi)[off] = h2;
    ((__nv_bfloat162*)g_klo)[off] = l2;
}

// ---------------- bf16 hi/lo split into K3-interleaved layout ---------------
__global__ __launch_bounds__(256) void split_kernel(const float* __restrict__ src,
                                                    __nv_bfloat16* __restrict__ dst,
                                                    int n)
{
    int i = blockIdx.x * 256 + threadIdx.x;
    if (i >= n) return;
    size_t r  = (size_t)(i >> 11);
    int    cc = i & 2047;
    float v = src[i];
    __nv_bfloat16 hi = __float2bfloat16(v);
    float hv = __bfloat162float(hi);
    __nv_bfloat16 lo = __float2bfloat16(v - hv);
    dst[r * K3 + cc]        = hi;
    dst[r * K3 + 2048 + cc] = lo;
}

// ---------------- bf16x3 GEMM v2: 256x128 CTA tile, 64x64 warp tile ---------
// C[m,n] = sum_k A[m,k] B[n,k]; A [Mx4096] split, B [2048x4096] split.
// 96 chunks of K=64 across 3 logical segments; 3-stage cp.async ring.
// vmode=1: blockIdx.z==2 writes bf16 hi/lo to g_vhi/g_vlo instead of fp32.
__global__ void __launch_bounds__(256, 1) mma_gemm2_kernel(
    const __nv_bfloat16* __restrict__ A,
    const __nv_bfloat16* __restrict__ B0, const __nv_bfloat16* __restrict__ B1,
    const __nv_bfloat16* __restrict__ B2,
    float* __restrict__ C0, float* __restrict__ C1, float* __restrict__ C2,
    int vmode)
{
    const __nv_bfloat16* Bw = (blockIdx.z == 0) ? B0 : (blockIdx.z == 1) ? B1 : B2;
    float*               Cw = (blockIdx.z == 0) ? C0 : (blockIdx.z == 1) ? C1 : C2;

    extern __shared__ __align__(16) char dynsm[];
    const uint32_t base = smem_u32(dynsm);

    const int t    = threadIdx.x;
    const int wid  = t >> 5;
    const int lane = t & 31;
    const int wm0  = (wid & 3) * 64;     // 4 m-slabs
    const int wn0  = (wid >> 2) * 64;    // 2 n-slabs

    const size_t m0 = (size_t)blockIdx.y * 256;
    const size_t n0 = (size_t)blockIdx.x * 128;
    const __nv_bfloat16* Ab = A  + m0 * K3;
    const __nv_bfloat16* Bb = Bw + n0 * K3;

    const int lrow = t >> 3;             // 0..31
    const int lseg = (t & 7) * 8;        // element offset of 16B seg

    float acc[4][8][4];
#pragma unroll
    for (int i = 0; i < 4; i++)
#pragma unroll
        for (int j = 0; j < 8; j++)
#pragma unroll
            for (int r = 0; r < 4; r++) acc[i][j][r] = 0.f;

    const int atile = lane >> 3;
    const int arow8 = (atile & 1) * 8;
    const int akof  = (atile >> 1) * 8;
    const int bnof  = (atile >> 1) * 8;
    const int bkof  = (atile & 1) * 8;
    const int l8    = lane & 7;

    auto issue = [&](int chunk, int stage) {
        const int seg = chunk >> 5;
        const int kin = (chunk & 31) << 6;
        const int kA  = ((seg == 2) ? 2048 : 0) + kin;
        const int kB  = ((seg == 1) ? 2048 : 0) + kin;
        const uint32_t aS = base + stage * A_STAGE;
        const uint32_t bS = base + B_OFF + stage * B_STAGE;
#pragma unroll
        for (int u = 0; u < 8; ++u) {
            int row = lrow + 32 * u;
            cp16(aS + (row * SAW + lseg) * 2, Ab + (size_t)row * K3 + kA + lseg);
        }
#pragma unroll
        for (int u = 0; u < 4; ++u) {
            int row = lrow + 32 * u;
            cp16(bS + (row * SAW + lseg) * 2, Bb + (size_t)row * K3 + kB + lseg);
        }
    };

    const int NC = 96;
    issue(0, 0);
    asm volatile("cp.async.commit_group;" ::: "memory");
    issue(1, 1);
    asm volatile("cp.async.commit_group;" ::: "memory");

    for (int c = 0; c < NC; ++c) {
        asm volatile("cp.async.wait_group 1;" ::: "memory");
        __syncthreads();
        if (c + 2 < NC) issue(c + 2, (c + 2) % 3);
        asm volatile("cp.async.commit_group;" ::: "memory");

        const uint32_t aS = base + (c % 3) * A_STAGE;
        const uint32_t bS = base + B_OFF + (c % 3) * B_STAGE;
#pragma unroll
        for (int kk = 0; kk < 64; kk += 16) {
            uint32_t af[4][4], bf[8][2];
#pragma unroll
            for (int i = 0; i < 4; ++i) {
                int row = wm0 + 16 * i + arow8 + l8;
                ldm_x4(aS + (uint32_t)(row * SAW + kk + akof) * 2,
                       af[i][0], af[i][1], af[i][2], af[i][3]);
            }
#pragma unroll
            for (int j = 0; j < 4; ++j) {
                int n = wn0 + 16 * j + bnof + l8;
                uint32_t r0, r1, r2, r3;
                ldm_x4(bS + (uint32_t)(n * SAW + kk + bkof) * 2, r0, r1, r2, r3);
                bf[2 * j + 0][0] = r0; bf[2 * j + 0][1] = r1;
                bf[2 * j + 1][0] = r2; bf[2 * j + 1][1] = r3;
            }
#pragma unroll
            for (int i = 0; i < 4; ++i)
#pragma unroll
                for (int j = 0; j < 8; ++j)
                    mma_bf16(acc[i][j], af[i], bf[j]);
        }
    }

    const int rbase = lane >> 2;
    const int cbase = (lane & 3) * 2;

    if (vmode && blockIdx.z == 2) {
        // write V hi/lo splits directly
#pragma unroll
        for (int i = 0; i < 4; ++i) {
#pragma unroll
            for (int j = 0; j < 8; ++j) {
                size_t row = m0 + wm0 + 16 * i + rbase;
                size_t col = n0 + wn0 + 8 * j + cbase;
#pragma unroll
                for (int hrow = 0; hrow < 2; ++hrow) {
                    float v0 = acc[i][j][hrow * 2 + 0];
                    float v1 = acc[i][j][hrow * 2 + 1];
                    __nv_bfloat162 h2, l2;
                    h2.x = __float2bfloat16(v0);
                    l2.x = __float2bfloat16(v0 - __bfloat162float(h2.x));
                    h2.y = __float2bfloat16(v1);
                    l2.y = __float2bfloat16(v1 - __bfloat162float(h2.y));
                    size_t o = (row + hrow * 8) * DM + col;
                    *(__nv_bfloat162*)(g_vhi + o) = h2;
                    *(__nv_bfloat162*)(g_vlo + o) = l2;
                }
            }
        }
    } else {
#pragma unroll
        for (int i = 0; i < 4; ++i) {
#pragma unroll
            for (int j = 0; j < 8; ++j) {
                size_t row = m0 + wm0 + 16 * i + rbase;
                size_t col = n0 + wn0 + 8 * j + cbase;
                *(float2*)(Cw + row * DM + col)       = make_float2(acc[i][j][0], acc[i][j][1]);
                *(float2*)(Cw + (row + 8) * DM + col) = make_float2(acc[i][j][2], acc[i][j][3]);
            }
        }
    }
}

// ---------------- scores via mma: S = (Q K^T)/sqrt(hd), bf16x3 split --------
__global__ void __launch_bounds__(256, 2) scores_mma_kernel()
{
    const int bn = blockIdx.x, bm = blockIdx.y, z = blockIdx.z;
    if (bn > bm) return;
    const int b = z >> 4, h = z & 15;

    __shared__ __align__(16) __nv_bfloat16 sm_a[2][128 * SA];
    __shared__ __align__(16) __nv_bfloat16 sm_b[2][128 * SA];

    const int t    = threadIdx.x;
    const int wid  = t >> 5;
    const int lane = t & 31;
    const int wm0  = (wid >> 2) * 64;
    const int wn0  = (wid & 3) * 32;

    const size_t arow = (size_t)(b * SEQ + bm * 128);
    const size_t brow = (size_t)(b * SEQ + bn * 128);
    const __nv_bfloat16* Aqh = g_qhi + arow * DM + h * HD;
    const __nv_bfloat16* Aql = g_qlo + arow * DM + h * HD;
    const __nv_bfloat16* Bkh = g_khi + brow * DM + h * HD;
    const __nv_bfloat16* Bkl = g_klo + brow * DM + h * HD;
    float* Cb = g_p + (size_t)z * SEQ * SEQ + (size_t)(bm * 128) * SEQ + bn * 128;

    const uint32_t sa0 = smem_u32(&sm_a[0][0]);
    const uint32_t sa1 = smem_u32(&sm_a[1][0]);
    const uint32_t sb0 = smem_u32(&sm_b[0][0]);
    const uint32_t sb1 = smem_u32(&sm_b[1][0]);

    const int lr0 = t >> 2, ls0 = t & 3;
    const int lr1 = lr0 + 64;

    float acc[4][4][4];
#pragma unroll
    for (int i = 0; i < 4; i++)
#pragma unroll
        for (int j = 0; j < 4; j++)
#pragma unroll
            for (int r = 0; r < 4; r++) acc[i][j][r] = 0.f;

    const int atile = lane >> 3;
    const int arow8 = (atile & 1) * 8;
    const int akof  = (atile >> 1) * 8;
    const int bnof  = (atile >> 1) * 8;
    const int bkof  = (atile & 1) * 8;
    const int l8    = lane & 7;

    const int NC = 12;
    {
        cp16(sa0 + (lr0 * SA + ls0 * 8) * 2, Aqh + (size_t)lr0 * DM + ls0 * 8);
        cp16(sb0 + (lr0 * SA + ls0 * 8) * 2, Bkh + (size_t)lr0 * DM + ls0 * 8);
        cp16(sa0 + (lr1 * SA + ls0 * 8) * 2, Aqh + (size_t)lr1 * DM + ls0 * 8);
        cp16(sb0 + (lr1 * SA + ls0 * 8) * 2, Bkh + (size_t)lr1 * DM + ls0 * 8);
        asm volatile("cp.async.commit_group;" ::: "memory");
    }

    for (int c = 0; c < NC; ++c) {
        const int buf = c & 1;
        const int cn  = c + 1;
        if (cn < NC) {
            const int nbuf = cn & 1;
            const uint32_t na = nbuf ? sa1 : sa0;
            const uint32_t nb = nbuf ? sb1 : sb0;
            const int seg = cn >> 2;
            const int kin = (cn & 3) << 5;
            const __nv_bfloat16* As = (seg == 2) ? Aql : Aqh;
            const __nv_bfloat16* Bs = (seg == 1) ? Bkl : Bkh;
            cp16(na + (lr0 * SA + ls0 * 8) * 2, As + (size_t)lr0 * DM + kin + ls0 * 8);
            cp16(nb + (lr0 * SA + ls0 * 8) * 2, Bs + (size_t)lr0 * DM + kin + ls0 * 8);
            cp16(na + (lr1 * SA + ls0 * 8) * 2, As + (size_t)lr1 * DM + kin + ls0 * 8);
            cp16(nb + (lr1 * SA + ls0 * 8) * 2, Bs + (size_t)lr1 * DM + kin + ls0 * 8);
            asm volatile("cp.async.commit_group;" ::: "memory");
            asm volatile("cp.async.wait_group 1;" ::: "memory");
        } else {
            asm volatile("cp.async.wait_group 0;" ::: "memory");
        }
        __syncthreads();

        const uint32_t ab = buf ? sa1 : sa0;
        const uint32_t bb = buf ? sb1 : sb0;

#pragma unroll
        for (int kk = 0; kk < 32; kk += 16) {
            uint32_t af[4][4], bf[4][2];
#pragma unroll
            for (int i = 0; i < 4; ++i) {
                int row = wm0 + 16 * i + arow8 + l8;
                ldm_x4(ab + (uint32_t)(row * SA + kk + akof) * 2,
                       af[i][0], af[i][1], af[i][2], af[i][3]);
            }
#pragma unroll
            for (int jp = 0; jp < 2; ++jp) {
                int n = wn0 + 16 * jp + bnof + l8;
                uint32_t r0, r1, r2, r3;
                ldm_x4(bb + (uint32_t)(n * SA + kk + bkof) * 2, r0, r1, r2, r3);
                bf[2 * jp + 0][0] = r0; bf[2 * jp + 0][1] = r1;
                bf[2 * jp + 1][0] = r2; bf[2 * jp + 1][1] = r3;
            }
#pragma unroll
            for (int i = 0; i < 4; ++i)
#pragma unroll
                for (int j = 0; j < 4; ++j)
                    mma_bf16(acc[i][j], af[i], bf[j]);
        }
        __syncthreads();
    }

    const float scale = 0.088388347648318447f;
    const int rbase = lane >> 2;
    const int cbase = (lane & 3) * 2;
#pragma unroll
    for (int i = 0; i < 4; ++i) {
#pragma unroll
        for (int j = 0; j < 4; ++j) {
            int row = wm0 + 16 * i + rbase;
            int col = wn0 + 8 * j + cbase;
            *(float2*)(Cb + (size_t)row * SEQ + col) =
                make_float2(acc[i][j][0] * scale, acc[i][j][1] * scale);
            *(float2*)(Cb + (size_t)(row + 8) * SEQ + col) =
                make_float2(acc[i][j][2] * scale, acc[i][j][3] * scale);
        }
    }
}

// ---------------- causal row softmax: fp32 scores -> bf16 hi/lo probs -------
__global__ __launch_bounds__(256) void softmax_kernel()
{
    const int q = blockIdx.x, z = blockIdx.y;
    const size_t rb = (size_t)z * SEQ * SEQ + (size_t)q * SEQ;
    const float* row = g_p + rb;
    __nv_bfloat16* ph = g_phi + rb;
    __nv_bfloat16* pl = g_plo + rb;
    const int L  = q + 1;
    const int Lz = ((q >> 7) + 1) << 7;
    __shared__ float red[256];
    const int tid = threadIdx.x;

    float m = -1e30f;
    for (int k = tid; k < L; k += 256) m = fmaxf(m, row[k]);
    red[tid] = m; __syncthreads();
    for (int s = 128; s > 0; s >>= 1) {
        if (tid < s) red[tid] = fmaxf(red[tid], red[tid + s]);
        __syncthreads();
    }
    const float rowmax = red[0];
    __syncthreads();

    float sum = 0.f;
    for (int k = tid; k < L; k += 256) sum += __expf(row[k] - rowmax);
    red[tid] = sum; __syncthreads();
    for (int s = 128; s > 0; s >>= 1) {
        if (tid < s) red[tid] += red[tid + s];
        __syncthreads();
    }
    const float inv = 1.0f / red[0];

    for (int k = tid; k < L; k += 256) {
        float p = __expf(row[k] - rowmax) * inv;
        __nv_bfloat16 hi = __float2bfloat16(p);
        ph[k] = hi;
        pl[k] = __float2bfloat16(p - __bfloat162float(hi));
    }
    const __nv_bfloat16 zz = __float2bfloat16(0.f);
    for (int k = L + tid; k < Lz; k += 256) { ph[k] = zz; pl[k] = zz; }
}

// ---------------- O = P V via mma; writes attn-out split (K3) directly ------
__global__ void __launch_bounds__(256, 2) pv_mma_kernel()
{
    const int bm = blockIdx.x, z = blockIdx.y;
    const int b = z >> 4, h = z & 15;

    __shared__ __align__(16) __nv_bfloat16 sm_a[2][128 * SA];
    __shared__ __align__(16) __nv_bfloat16 sm_b[2][32 * SB];

    const int t    = threadIdx.x;
    const int wid  = t >> 5;
    const int lane = t & 31;
    const int wm0  = (wid >> 2) * 64;
    const int wn0  = (wid & 3) * 32;

    const size_t pbase = (size_t)z * SEQ * SEQ + (size_t)(bm * 128) * SEQ;
    const __nv_bfloat16* Aph = g_phi + pbase;
    const __nv_bfloat16* Apl = g_plo + pbase;
    const __nv_bfloat16* Bvh = g_vhi + (size_t)(b * SEQ) * DM + h * HD;
    const __nv_bfloat16* Bvl = g_vlo + (size_t)(b * SEQ) * DM + h * HD;

    const uint32_t sa0 = smem_u32(&sm_a[0][0]);
    const uint32_t sa1 = smem_u32(&sm_a[1][0]);
    const uint32_t sb0 = smem_u32(&sm_b[0][0]);
    const uint32_t sb1 = smem_u32(&sm_b[1][0]);

    const int alr0 = t >> 2, als0 = t & 3;
    const int alr1 = alr0 + 64;
    const int blr0 = t >> 4, bls0 = t & 15;
    const int blr1 = blr0 + 16, bls1 = bls0;

    float acc[4][4][4];
#pragma unroll
    for (int i = 0; i < 4; i++)
#pragma unroll
        for (int j = 0; j < 4; j++)
#pragma unroll
            for (int r = 0; r < 4; r++) acc[i][j][r] = 0.f;

    const int atile = lane >> 3;
    const int arow8 = (atile & 1) * 8;
    const int akof  = (atile >> 1) * 8;
    const int bkof  = (atile & 1) * 8;
    const int bnof  = (atile >> 1) * 8;
    const int l8    = lane & 7;

    const int npc = (bm + 1) * 4;
    const int NC  = 3 * npc;
    {
        cp16(sa0 + (alr0 * SA + als0 * 8) * 2, Aph + (size_t)alr0 * SEQ + als0 * 8);
        cp16(sa0 + (alr1 * SA + als0 * 8) * 2, Aph + (size_t)alr1 * SEQ + als0 * 8);
        cp16(sb0 + (blr0 * SB + bls0 * 8) * 2, Bvh + (size_t)blr0 * DM + bls0 * 8);
        cp16(sb0 + (blr1 * SB + bls1 * 8) * 2, Bvh + (size_t)blr1 * DM + bls1 * 8);
        asm volatile("cp.async.commit_group;" ::: "memory");
    }

    for (int c = 0; c < NC; ++c) {
        const int buf = c & 1;
        const int cn  = c + 1;
        if (cn < NC) {
            const int nbuf = cn & 1;
            const uint32_t na = nbuf ? sa1 : sa0;
            const uint32_t nb = nbuf ? sb1 : sb0;
            const int seg = (cn >= 2 * npc) ? 2 : ((cn >= npc) ? 1 : 0);
            const int kin = (cn - seg * npc) << 5;
            const __nv_bfloat16* As = (seg == 2) ? Apl : Aph;
            const __nv_bfloat16* Bs = (seg == 1) ? Bvl : Bvh;
            cp16(na + (alr0 * SA + als0 * 8) * 2, As + (size_t)alr0 * SEQ + kin + als0 * 8);
            cp16(na + (alr1 * SA + als0 * 8) * 2, As + (size_t)alr1 * SEQ + kin + als0 * 8);
            cp16(nb + (blr0 * SB + bls0 * 8) * 2, Bs + (size_t)(kin + blr0) * DM + bls0 * 8);
            cp16(nb + (blr1 * SB + bls1 * 8) * 2, Bs + (size_t)(kin + blr1) * DM + bls1 * 8);
            asm volatile("cp.async.commit_group;" ::: "memory");
            asm volatile("cp.async.wait_group 1;" ::: "memory");
        } else {
            asm volatile("cp.async.wait_group 0;" ::: "memory");
        }
        __syncthreads();

        const uint32_t ab = buf ? sa1 : sa0;
        const uint32_t bb = buf ? sb1 : sb0;

#pragma unroll
        for (int kk = 0; kk < 32; kk += 16) {
            uint32_t af[4][4], bf[4][2];
#pragma unroll
            for (int i = 0; i < 4; ++i) {
                int row = wm0 + 16 * i + arow8 + l8;
                ldm_x4(ab + (uint32_t)(row * SA + kk + akof) * 2,
                       af[i][0], af[i][1], af[i][2], af[i][3]);
            }
#pragma unroll
            for (int jp = 0; jp < 2; ++jp) {
                int srow = kk + bkof + l8;
                int scol = wn0 + 16 * jp + bnof;
                uint32_t r0, r1, r2, r3;
                ldm_x4t(bb + (uint32_t)(srow * SB + scol) * 2, r0, r1, r2, r3);
                bf[2 * jp + 0][0] = r0; bf[2 * jp + 0][1] = r1;
                bf[2 * jp + 1][0] = r2; bf[2 * jp + 1][1] = r3;
            }
#pragma unroll
            for (int i = 0; i < 4; ++i)
#pragma unroll
                for (int j = 0; j < 4; ++j)
                    mma_bf16(acc[i][j], af[i], bf[j]);
        }
        __syncthreads();
    }

    const int rbase = lane >> 2;
    const int cbase = (lane & 3) * 2;
#pragma unroll
    for (int i = 0; i < 4; ++i) {
#pragma unroll
        for (int j = 0; j < 4; ++j) {
            int row = wm0 + 16 * i + rbase;
            int col = wn0 + 8 * j + cbase;
#pragma unroll
            for (int hrow = 0; hrow < 2; ++hrow) {
                float v0 = acc[i][j][hrow * 2 + 0];
                float v1 = acc[i][j][hrow * 2 + 1];
                __nv_bfloat162 h2, l2;
                h2.x = __float2bfloat16(v0);
                l2.x = __float2bfloat16(v0 - __bfloat162float(h2.x));
                h2.y = __float2bfloat16(v1);
                l2.y = __float2bfloat16(v1 - __bfloat162float(h2.y));
                size_t grow = (size_t)(b * SEQ + bm * 128 + row + hrow * 8);
                size_t gcol = (size_t)(h * HD + col);
                *(__nv_bfloat162*)(g_aos + grow * K3 + gcol)        = h2;
                *(__nv_bfloat162*)(g_aos + grow * K3 + 2048 + gcol) = l2;
            }
        }
    }
}

// ---------------- launch ----------------------------------------------------
extern "C" void kernel_launch(void* const* d_in, const int* in_sizes, int n_in,
                              void* d_out, int out_size)
{
    const float* x  = (const float*)d_in[0];
    const float* Wq = (const float*)d_in[2];
    const float* Wk = (const float*)d_in[3];
    const float* Wv = (const float*)d_in[4];
    const float* Wo = (const float*)d_in[5];
    float* out = (float*)d_out;

    float *pq, *pk;
    __nv_bfloat16 *pxs, *pws, *paos;
    cudaGetSymbolAddress((void**)&pq,   g_q);
    cudaGetSymbolAddress((void**)&pk,   g_k);
    cudaGetSymbolAddress((void**)&pxs,  g_xs);
    cudaGetSymbolAddress((void**)&pws,  g_ws);
    cudaGetSymbolAddress((void**)&paos, g_aos);

    cudaFuncSetAttribute(mma_gemm2_kernel,
                         cudaFuncAttributeMaxDynamicSharedMemorySize, GEMM2_SMEM);

    rope_table_kernel<<<SEQ, HD / 2>>>();

    split_kernel<<<(MTOT * DM) / 256, 256>>>(x, pxs, MTOT * DM);
    split_kernel<<<(DM * DM) / 256, 256>>>(Wq, pws + 0ULL * DM * K3, DM * DM);
    split_kernel<<<(DM * DM) / 256, 256>>>(Wk, pws + 1ULL * DM * K3, DM * DM);
    split_kernel<<<(DM * DM) / 256, 256>>>(Wv, pws + 2ULL * DM * K3, DM * DM);
    split_kernel<<<(DM * DM) / 256, 256>>>(Wo, pws + 3ULL * DM * K3, DM * DM);

    // QKV: 256x128 tiles, z=2 (V) writes bf16 splits directly
    mma_gemm2_kernel<<<dim3(16, 16, 3), 256, GEMM2_SMEM>>>(
        pxs, pws + 0ULL * DM * K3, pws + 1ULL * DM * K3, pws + 2ULL * DM * K3,
        pq, pk, pq, 1);

    rope_apply_kernel<<<(MTOT * (DM / 2)) / 256, 256>>>();

    scores_mma_kernel<<<dim3(16, 16, 32), 256>>>();
    softmax_kernel<<<dim3(SEQ, 32), 256>>>();
    pv_mma_kernel<<<dim3(16, 32), 256>>>();

    // out-projection from fused attn-out split
    mma_gemm2_kernel<<<dim3(16, 16, 1), 256, GEMM2_SMEM>>>(
        paos, pws + 3ULL * DM * K3, pws + 3ULL * DM * K3, pws + 3ULL * DM * K3,
        out, out, out, 0);
}

// round 9
// speedup vs baseline: 2.3373x; 1.1419x over previous
#include <cuda_runtime.h>
#include <cuda_bf16.h>
#include <math.h>
#include <stdint.h>

#define SEQ    2048
#define DM     2048
#define NH     16
#define HD     128
#define NB     2
#define MTOT   (NB * SEQ)          // 4096
#define K3     4096                // split width: [hi(2048) | lo(2048)]
#define SAW    72                  // gemm2 smem row stride (144B)
#define SF     136                 // flash smem row stride in bf16 (272B)

// gemm2 smem layout (dynamic)
#define A_STAGE (256 * SAW * 2)    // 36864 B
#define B_STAGE (128 * SAW * 2)    // 18432 B
#define B_OFF   (3 * A_STAGE)
#define GEMM2_SMEM (3 * A_STAGE + 3 * B_STAGE)   // 165888 B

// flash smem layout (dynamic): Q hi/lo resident + 2 KV stages
#define F_ROWB   (SF * 2)                 // 272 B per row
#define F_QHI    0
#define F_QLO    (128 * F_ROWB)           // 34816
#define F_KV0    (2 * 128 * F_ROWB)       // 69632
#define F_OKHI   0
#define F_OKLO   (64 * F_ROWB)            // 17408
#define F_OVHI   (2 * 64 * F_ROWB)        // 34816
#define F_OVLO   (3 * 64 * F_ROWB)        // 52224
#define F_STG    (4 * 64 * F_ROWB)        // 69632
#define FLASH_SMEM (F_KV0 + 2 * F_STG)    // 208896 B

// ---------------- scratch (device globals: allocation-free rule) ------------
static __device__ float g_q [(size_t)MTOT * DM];            // 32 MB
static __device__ float g_k [(size_t)MTOT * DM];            // 32 MB
static __device__ float g_cos[SEQ * (HD / 2)];
static __device__ float g_sin[SEQ * (HD / 2)];
static __device__ __nv_bfloat16 g_xs [(size_t)MTOT * K3];   // x split (K3 layout)
static __device__ __nv_bfloat16 g_ws [4ULL * DM * K3];      // W splits (K3 layout)
static __device__ __nv_bfloat16 g_aos[(size_t)MTOT * K3];   // attn-out split (K3)
static __device__ __nv_bfloat16 g_qhi[(size_t)MTOT * DM];
static __device__ __nv_bfloat16 g_qlo[(size_t)MTOT * DM];
static __device__ __nv_bfloat16 g_khi[(size_t)MTOT * DM];
static __device__ __nv_bfloat16 g_klo[(size_t)MTOT * DM];
static __device__ __nv_bfloat16 g_vhi[(size_t)MTOT * DM];
static __device__ __nv_bfloat16 g_vlo[(size_t)MTOT * DM];

// ---------------- PTX helpers (baseline ISA only) ---------------------------
__device__ __forceinline__ uint32_t smem_u32(const void* p) {
    uint32_t a;
    asm("{ .reg .u64 t; cvta.to.shared.u64 t, %1; cvt.u32.u64 %0, t; }"
        : "=r"(a) : "l"(p));
    return a;
}

__device__ __forceinline__ void cp16(uint32_t saddr, const void* g) {
    asm volatile("cp.async.cg.shared.global [%0], [%1], 16;"
                 :: "r"(saddr), "l"(g));
}

__device__ __forceinline__ void ldm_x4(uint32_t addr, uint32_t& r0, uint32_t& r1,
                                       uint32_t& r2, uint32_t& r3) {
    asm volatile("ldmatrix.sync.aligned.m8n8.x4.shared.b16 {%0,%1,%2,%3}, [%4];"
                 : "=r"(r0), "=r"(r1), "=r"(r2), "=r"(r3) : "r"(addr));
}

__device__ __forceinline__ void ldm_x4t(uint32_t addr, uint32_t& r0, uint32_t& r1,
                                        uint32_t& r2, uint32_t& r3) {
    asm volatile("ldmatrix.sync.aligned.m8n8.x4.trans.shared.b16 {%0,%1,%2,%3}, [%4];"
                 : "=r"(r0), "=r"(r1), "=r"(r2), "=r"(r3) : "r"(addr));
}

__device__ __forceinline__ void mma_bf16(float* c, const uint32_t* a, const uint32_t* b) {
    asm volatile(
        "mma.sync.aligned.m16n8k16.row.col.f32.bf16.bf16.f32 "
        "{%0,%1,%2,%3}, {%4,%5,%6,%7}, {%8,%9}, {%0,%1,%2,%3};"
        : "+f"(c[0]), "+f"(c[1]), "+f"(c[2]), "+f"(c[3])
        : "r"(a[0]), "r"(a[1]), "r"(a[2]), "r"(a[3]), "r"(b[0]), "r"(b[1]));
}

__device__ __forceinline__ uint32_t pack_bf16x2(float a, float b) {
    __nv_bfloat162 h = __floats2bfloat162_rn(a, b);
    return *(uint32_t*)&h;
}

// ---------------- RoPE table (match jnp: fp32 angle, accurate trig) ---------
__global__ void rope_table_kernel()
{
    int s = blockIdx.x;
    int i = threadIdx.x;
    double e    = ((double)(2 * i)) / (double)HD;
    double powd = pow(10000.0, e);
    float  invf = (float)(1.0 / powd);
    float  fr   = (float)s * invf;
    double a    = (double)fr;
    g_cos[s * (HD / 2) + i] = (float)cos(a);
    g_sin[s * (HD / 2) + i] = (float)sin(a);
}

// RoPE apply fused with hi/lo bf16 split.
__global__ __launch_bounds__(256) void rope_apply_kernel()
{
    size_t idx = (size_t)blockIdx.x * 256 + threadIdx.x;
    int    i   = (int)(idx & 63);
    size_t cp  = idx & 1023;
    size_t m   = idx >> 10;
    int    s   = (int)(m & (SEQ - 1));
    float  c   = g_cos[s * (HD / 2) + i];
    float  sn  = g_sin[s * (HD / 2) + i];
    size_t off = m * (DM / 2) + cp;

    float2 qv = ((const float2*)g_q)[off];
    float qx = qv.x * c - qv.y * sn;
    float qy = qv.x * sn + qv.y * c;
    float2 kv = ((const float2*)g_k)[off];
    float kx = kv.x * c - kv.y * sn;
    float ky = kv.x * sn + kv.y * c;

    __nv_bfloat162 h2, l2;
    h2.x = __float2bfloat16(qx); l2.x = __float2bfloat16(qx - __bfloat162float(h2.x));
    h2.y = __float2bfloat16(qy); l2.y = __float2bfloat16(qy - __bfloat162float(h2.y));
    ((__nv_bfloat162*)g_qhi)[off] = h2;
    ((__nv_bfloat162*)g_qlo)[off] = l2;

    h2.x = __float2bfloat16(kx); l2.x = __float2bfloat16(kx - __bfloat162float(h2.x));
    h2.y = __float2bfloat16(ky); l2.y = __float2bfloat16(ky - __bfloat162float(h2.y));
    ((__nv_bfloat162*)g_khi)[off] = h2;
    ((__nv_bfloat162*)g_klo)[off] = l2;
}

// ---------------- bf16 hi/lo split into K3-interleaved layout ---------------
__global__ __launch_bounds__(256) void split_kernel(const float* __restrict__ src,
                                                    __nv_bfloat16* __restrict__ dst,
                                                    int n)
{
    int i = blockIdx.x * 256 + threadIdx.x;
    if (i >= n) return;
    size_t r  = (size_t)(i >> 11);
    int    cc = i & 2047;
    float v = src[i];
    __nv_bfloat16 hi = __float2bfloat16(v);
    float hv = __bfloat162float(hi);
    __nv_bfloat16 lo = __float2bfloat16(v - hv);
    dst[r * K3 + cc]        = hi;
    dst[r * K3 + 2048 + cc] = lo;
}

// ---------------- bf16x3 GEMM: 256x128 CTA tile, 64x64 warp tile ------------
__global__ void __launch_bounds__(256, 1) mma_gemm2_kernel(
    const __nv_bfloat16* __restrict__ A,
    const __nv_bfloat16* __restrict__ B0, const __nv_bfloat16* __restrict__ B1,
    const __nv_bfloat16* __restrict__ B2,
    float* __restrict__ C0, float* __restrict__ C1, float* __restrict__ C2,
    int vmode)
{
    const __nv_bfloat16* Bw = (blockIdx.z == 0) ? B0 : (blockIdx.z == 1) ? B1 : B2;
    float*               Cw = (blockIdx.z == 0) ? C0 : (blockIdx.z == 1) ? C1 : C2;

    extern __shared__ __align__(16) char dynsm[];
    const uint32_t base = smem_u32(dynsm);

    const int t    = threadIdx.x;
    const int wid  = t >> 5;
    const int lane = t & 31;
    const int wm0  = (wid & 3) * 64;
    const int wn0  = (wid >> 2) * 64;

    const size_t m0 = (size_t)blockIdx.y * 256;
    const size_t n0 = (size_t)blockIdx.x * 128;
    const __nv_bfloat16* Ab = A  + m0 * K3;
    const __nv_bfloat16* Bb = Bw + n0 * K3;

    const int lrow = t >> 3;
    const int lseg = (t & 7) * 8;

    float acc[4][8][4];
#pragma unroll
    for (int i = 0; i < 4; i++)
#pragma unroll
        for (int j = 0; j < 8; j++)
#pragma unroll
            for (int r = 0; r < 4; r++) acc[i][j][r] = 0.f;

    const int atile = lane >> 3;
    const int arow8 = (atile & 1) * 8;
    const int akof  = (atile >> 1) * 8;
    const int bnof  = (atile >> 1) * 8;
    const int bkof  = (atile & 1) * 8;
    const int l8    = lane & 7;

    auto issue = [&](int chunk, int stage) {
        const int seg = chunk >> 5;
        const int kin = (chunk & 31) << 6;
        const int kA  = ((seg == 2) ? 2048 : 0) + kin;
        const int kB  = ((seg == 1) ? 2048 : 0) + kin;
        const uint32_t aS = base + stage * A_STAGE;
        const uint32_t bS = base + B_OFF + stage * B_STAGE;
#pragma unroll
        for (int u = 0; u < 8; ++u) {
            int row = lrow + 32 * u;
            cp16(aS + (row * SAW + lseg) * 2, Ab + (size_t)row * K3 + kA + lseg);
        }
#pragma unroll
        for (int u = 0; u < 4; ++u) {
            int row = lrow + 32 * u;
            cp16(bS + (row * SAW + lseg) * 2, Bb + (size_t)row * K3 + kB + lseg);
        }
    };

    const int NC = 96;
    issue(0, 0);
    asm volatile("cp.async.commit_group;" ::: "memory");
    issue(1, 1);
    asm volatile("cp.async.commit_group;" ::: "memory");

    for (int c = 0; c < NC; ++c) {
        asm volatile("cp.async.wait_group 1;" ::: "memory");
        __syncthreads();
        if (c + 2 < NC) issue(c + 2, (c + 2) % 3);
        asm volatile("cp.async.commit_group;" ::: "memory");

        const uint32_t aS = base + (c % 3) * A_STAGE;
        const uint32_t bS = base + B_OFF + (c % 3) * B_STAGE;
#pragma unroll
        for (int kk = 0; kk < 64; kk += 16) {
            uint32_t af[4][4], bf[8][2];
#pragma unroll
            for (int i = 0; i < 4; ++i) {
                int row = wm0 + 16 * i + arow8 + l8;
                ldm_x4(aS + (uint32_t)(row * SAW + kk + akof) * 2,
                       af[i][0], af[i][1], af[i][2], af[i][3]);
            }
#pragma unroll
            for (int j = 0; j < 4; ++j) {
                int n = wn0 + 16 * j + bnof + l8;
                uint32_t r0, r1, r2, r3;
                ldm_x4(bS + (uint32_t)(n * SAW + kk + bkof) * 2, r0, r1, r2, r3);
                bf[2 * j + 0][0] = r0; bf[2 * j + 0][1] = r1;
                bf[2 * j + 1][0] = r2; bf[2 * j + 1][1] = r3;
            }
#pragma unroll
            for (int i = 0; i < 4; ++i)
#pragma unroll
                for (int j = 0; j < 8; ++j)
                    mma_bf16(acc[i][j], af[i], bf[j]);
        }
    }

    const int rbase = lane >> 2;
    const int cbase = (lane & 3) * 2;

    if (vmode && blockIdx.z == 2) {
#pragma unroll
        for (int i = 0; i < 4; ++i) {
#pragma unroll
            for (int j = 0; j < 8; ++j) {
                size_t row = m0 + wm0 + 16 * i + rbase;
                size_t col = n0 + wn0 + 8 * j + cbase;
#pragma unroll
                for (int hrow = 0; hrow < 2; ++hrow) {
                    float v0 = acc[i][j][hrow * 2 + 0];
                    float v1 = acc[i][j][hrow * 2 + 1];
                    __nv_bfloat162 h2, l2;
                    h2.x = __float2bfloat16(v0);
                    l2.x = __float2bfloat16(v0 - __bfloat162float(h2.x));
                    h2.y = __float2bfloat16(v1);
                    l2.y = __float2bfloat16(v1 - __bfloat162float(h2.y));
                    size_t o = (row + hrow * 8) * DM + col;
                    *(__nv_bfloat162*)(g_vhi + o) = h2;
                    *(__nv_bfloat162*)(g_vlo + o) = l2;
                }
            }
        }
    } else {
#pragma unroll
        for (int i = 0; i < 4; ++i) {
#pragma unroll
            for (int j = 0; j < 8; ++j) {
                size_t row = m0 + wm0 + 16 * i + rbase;
                size_t col = n0 + wn0 + 8 * j + cbase;
                *(float2*)(Cw + row * DM + col)       = make_float2(acc[i][j][0], acc[i][j][1]);
                *(float2*)(Cw + (row + 8) * DM + col) = make_float2(acc[i][j][2], acc[i][j][3]);
            }
        }
    }
}

// ---------------- fused flash attention: S -> online softmax -> PV ----------
// grid (16 qtiles [reversed], 32 bh). CTA: 128 q-rows x full head. 8 warps,
// warp = 16 q-rows. K/V processed in 64-key double-buffered stages.
// Writes attn-out bf16 hi/lo in K3 layout (input of out-projection).
__global__ void __launch_bounds__(256, 1) flash_kernel()
{
    const int bm = 15 - (int)blockIdx.x;     // heavy tiles first
    const int z  = blockIdx.y;
    const int b  = z >> 4, h = z & 15;

    extern __shared__ __align__(16) char dynsm[];
    const uint32_t base = smem_u32(dynsm);

    const int t    = threadIdx.x;
    const int wid  = t >> 5;
    const int lane = t & 31;
    const int wr   = wid * 16;               // warp q-row base

    const size_t qrow0 = (size_t)(b * SEQ + bm * 128);
    const size_t kvcol = (size_t)h * HD;

    const int atile = lane >> 3, l8 = lane & 7;
    const int arow8 = (atile & 1) * 8, akof = (atile >> 1) * 8;
    const int bnof  = (atile >> 1) * 8, bkof = (atile & 1) * 8;

    // Q hi/lo -> smem (grouped with stage 0)
#pragma unroll
    for (int u = 0; u < 8; ++u) {
        int g = t + u * 256;                 // 0..2047
        int row = g >> 4;
        int gc  = (g & 15) * 8;
        uint32_t so = (uint32_t)(row * SF + gc) * 2;
        cp16(base + F_QHI + so, g_qhi + (qrow0 + row) * DM + kvcol + gc);
        cp16(base + F_QLO + so, g_qlo + (qrow0 + row) * DM + kvcol + gc);
    }

    auto issueKV = [&](int kt, int stage) {
        uint32_t sb = base + F_KV0 + (uint32_t)stage * F_STG;
        size_t kr0 = (size_t)(b * SEQ + kt * 64);
#pragma unroll
        for (int u = 0; u < 4; ++u) {
            int g = t + u * 256;             // 0..1023
            int row = g >> 4;
            int gc  = (g & 15) * 8;
            size_t off  = (kr0 + row) * DM + kvcol + gc;
            uint32_t so = (uint32_t)(row * SF + gc) * 2;
            cp16(sb + F_OKHI + so, g_khi + off);
            cp16(sb + F_OKLO + so, g_klo + off);
            cp16(sb + F_OVHI + so, g_vhi + off);
            cp16(sb + F_OVLO + so, g_vlo + off);
        }
    };

    const int KT = 2 * bm + 2;
    issueKV(0, 0);
    asm volatile("cp.async.commit_group;" ::: "memory");
    issueKV(1, 1);
    asm volatile("cp.async.commit_group;" ::: "memory");

    float m0 = -1e30f, m1 = -1e30f, l0 = 0.f, l1 = 0.f;
    float acc_o[16][4];
#pragma unroll
    for (int j = 0; j < 16; ++j)
#pragma unroll
        for (int r = 0; r < 4; ++r) acc_o[j][r] = 0.f;

    for (int kt = 0; kt < KT; ++kt) {
        if (kt + 1 < KT) {
            asm volatile("cp.async.wait_group 1;" ::: "memory");
        } else {
            asm volatile("cp.async.wait_group 0;" ::: "memory");
        }
        __syncthreads();
        const uint32_t sS = base + F_KV0 + (uint32_t)(kt & 1) * F_STG;

        // ---- S = Q.K^T (3-term bf16 split, K_eff = 384) ----
        float s[8][4];
#pragma unroll
        for (int j = 0; j < 8; ++j)
#pragma unroll
            for (int r = 0; r < 4; ++r) s[j][r] = 0.f;

#pragma unroll
        for (int ks = 0; ks < 24; ++ks) {
            const int seg = ks >> 3;
            const int kc  = (ks & 7) * 16;
            const uint32_t qb = base + ((seg == 2) ? F_QLO : F_QHI);
            const uint32_t kb = sS + ((seg == 1) ? F_OKLO : F_OKHI);
            uint32_t af[4];
            ldm_x4(qb + (uint32_t)((wr + arow8 + l8) * SF + kc + akof) * 2,
                   af[0], af[1], af[2], af[3]);
            uint32_t bf[8][2];
#pragma unroll
            for (int j4 = 0; j4 < 4; ++j4) {
                uint32_t r0, r1, r2, r3;
                ldm_x4(kb + (uint32_t)((j4 * 16 + bnof + l8) * SF + kc + bkof) * 2,
                       r0, r1, r2, r3);
                bf[2 * j4 + 0][0] = r0; bf[2 * j4 + 0][1] = r1;
                bf[2 * j4 + 1][0] = r2; bf[2 * j4 + 1][1] = r3;
            }
#pragma unroll
            for (int j = 0; j < 8; ++j)
                mma_bf16(s[j], af, bf[j]);
        }

        // scale + causal mask
        const float sc = 0.088388347648318447f;
#pragma unroll
        for (int j = 0; j < 8; ++j)
#pragma unroll
            for (int r = 0; r < 4; ++r) s[j][r] *= sc;

        if (kt >= 2 * bm) {
            const int rg0 = bm * 128 + wr + (lane >> 2);
            const int cb  = kt * 64 + (lane & 3) * 2;
#pragma unroll
            for (int j = 0; j < 8; ++j) {
                int c0 = cb + j * 8, c1 = c0 + 1;
                if (c0 > rg0)     s[j][0] = -1e30f;
                if (c1 > rg0)     s[j][1] = -1e30f;
                if (c0 > rg0 + 8) s[j][2] = -1e30f;
                if (c1 > rg0 + 8) s[j][3] = -1e30f;
            }
        }

        // ---- online softmax (rows in-warp; cols spread over lane&3) ----
        float tm0 = -1e30f, tm1 = -1e30f;
#pragma unroll
        for (int j = 0; j < 8; ++j) {
            tm0 = fmaxf(tm0, fmaxf(s[j][0], s[j][1]));
            tm1 = fmaxf(tm1, fmaxf(s[j][2], s[j][3]));
        }
        tm0 = fmaxf(tm0, __shfl_xor_sync(0xffffffffu, tm0, 1));
        tm0 = fmaxf(tm0, __shfl_xor_sync(0xffffffffu, tm0, 2));
        tm1 = fmaxf(tm1, __shfl_xor_sync(0xffffffffu, tm1, 1));
        tm1 = fmaxf(tm1, __shfl_xor_sync(0xffffffffu, tm1, 2));

        const float mn0 = fmaxf(m0, tm0), mn1 = fmaxf(m1, tm1);
        const float f0 = __expf(m0 - mn0), f1 = __expf(m1 - mn1);
        m0 = mn0; m1 = mn1;

        uint32_t p01h[8], p23h[8], p01l[8], p23l[8];
        float rs0 = 0.f, rs1 = 0.f;
#pragma unroll
        for (int j = 0; j < 8; ++j) {
            float pa = __expf(s[j][0] - m0);
            float pb = __expf(s[j][1] - m0);
            float pc = __expf(s[j][2] - m1);
            float pd = __expf(s[j][3] - m1);
            rs0 += pa + pb; rs1 += pc + pd;
            __nv_bfloat16 ha = __float2bfloat16(pa), hb = __float2bfloat16(pb);
            __nv_bfloat16 hc = __float2bfloat16(pc), hd = __float2bfloat16(pd);
            p01h[j] = pack_bf16x2(__bfloat162float(ha), __bfloat162float(hb));
            p23h[j] = pack_bf16x2(__bfloat162float(hc), __bfloat162float(hd));
            p01l[j] = pack_bf16x2(pa - __bfloat162float(ha), pb - __bfloat162float(hb));
            p23l[j] = pack_bf16x2(pc - __bfloat162float(hc), pd - __bfloat162float(hd));
        }
        rs0 += __shfl_xor_sync(0xffffffffu, rs0, 1);
        rs0 += __shfl_xor_sync(0xffffffffu, rs0, 2);
        rs1 += __shfl_xor_sync(0xffffffffu, rs1, 1);
        rs1 += __shfl_xor_sync(0xffffffffu, rs1, 2);
        l0 = l0 * f0 + rs0;
        l1 = l1 * f1 + rs1;

#pragma unroll
        for (int j = 0; j < 16; ++j) {
            acc_o[j][0] *= f0; acc_o[j][1] *= f0;
            acc_o[j][2] *= f1; acc_o[j][3] *= f1;
        }

        // ---- O += Phi.Vhi + Phi.Vlo + Plo.Vhi ----
#pragma unroll
        for (int kk = 0; kk < 4; ++kk) {
            uint32_t ah[4] = {p01h[2 * kk], p23h[2 * kk], p01h[2 * kk + 1], p23h[2 * kk + 1]};
            uint32_t al[4] = {p01l[2 * kk], p23l[2 * kk], p01l[2 * kk + 1], p23l[2 * kk + 1]};
#pragma unroll
            for (int jn = 0; jn < 8; ++jn) {
                uint32_t srow = (uint32_t)(kk * 16 + bkof + l8);
                uint32_t scol = (uint32_t)(jn * 16 + bnof);
                uint32_t h0, h1, h2r, h3, q0, q1, q2, q3;
                ldm_x4t(sS + F_OVHI + (srow * SF + scol) * 2, h0, h1, h2r, h3);
                ldm_x4t(sS + F_OVLO + (srow * SF + scol) * 2, q0, q1, q2, q3);
                uint32_t bh0[2] = {h0, h1}, bh1[2] = {h2r, h3};
                uint32_t bl0[2] = {q0, q1}, bl1[2] = {q2, q3};
                mma_bf16(acc_o[2 * jn + 0], ah, bh0);
                mma_bf16(acc_o[2 * jn + 0], ah, bl0);
                mma_bf16(acc_o[2 * jn + 0], al, bh0);
                mma_bf16(acc_o[2 * jn + 1], ah, bh1);
                mma_bf16(acc_o[2 * jn + 1], ah, bl1);
                mma_bf16(acc_o[2 * jn + 1], al, bh1);
            }
        }

        __syncthreads();
        if (kt + 2 < KT) issueKV(kt + 2, kt & 1);
        asm volatile("cp.async.commit_group;" ::: "memory");
    }

    // ---- epilogue: O/l -> bf16 hi/lo into g_aos (K3 layout) ----
    const float i0 = 1.0f / l0, i1 = 1.0f / l1;
    const size_t grow0 = qrow0 + wr + (lane >> 2);
    const int    cb    = (lane & 3) * 2;
#pragma unroll
    for (int j = 0; j < 16; ++j) {
        size_t gcol = kvcol + j * 8 + cb;
        {
            float v0 = acc_o[j][0] * i0, v1 = acc_o[j][1] * i0;
            __nv_bfloat162 h2, l2;
            h2.x = __float2bfloat16(v0);
            l2.x = __float2bfloat16(v0 - __bfloat162float(h2.x));
            h2.y = __float2bfloat16(v1);
            l2.y = __float2bfloat16(v1 - __bfloat162float(h2.y));
            *(__nv_bfloat162*)(g_aos + grow0 * K3 + gcol)        = h2;
            *(__nv_bfloat162*)(g_aos + grow0 * K3 + 2048 + gcol) = l2;
        }
        {
            float v0 = acc_o[j][2] * i1, v1 = acc_o[j][3] * i1;
            __nv_bfloat162 h2, l2;
            h2.x = __float2bfloat16(v0);
            l2.x = __float2bfloat16(v0 - __bfloat162float(h2.x));
            h2.y = __float2bfloat16(v1);
            l2.y = __float2bfloat16(v1 - __bfloat162float(h2.y));
            *(__nv_bfloat162*)(g_aos + (grow0 + 8) * K3 + gcol)        = h2;
            *(__nv_bfloat162*)(g_aos + (grow0 + 8) * K3 + 2048 + gcol) = l2;
        }
    }
}

// ---------------- launch ----------------------------------------------------
extern "C" void kernel_launch(void* const* d_in, const int* in_sizes, int n_in,
                              void* d_out, int out_size)
{
    const float* x  = (const float*)d_in[0];
    const float* Wq = (const float*)d_in[2];
    const float* Wk = (const float*)d_in[3];
    const float* Wv = (const float*)d_in[4];
    const float* Wo = (const float*)d_in[5];
    float* out = (float*)d_out;

    float *pq, *pk;
    __nv_bfloat16 *pxs, *pws, *paos;
    cudaGetSymbolAddress((void**)&pq,   g_q);
    cudaGetSymbolAddress((void**)&pk,   g_k);
    cudaGetSymbolAddress((void**)&pxs,  g_xs);
    cudaGetSymbolAddress((void**)&pws,  g_ws);
    cudaGetSymbolAddress((void**)&paos, g_aos);

    cudaFuncSetAttribute(mma_gemm2_kernel,
                         cudaFuncAttributeMaxDynamicSharedMemorySize, GEMM2_SMEM);
    cudaFuncSetAttribute(flash_kernel,
                         cudaFuncAttributeMaxDynamicSharedMemorySize, FLASH_SMEM);

    rope_table_kernel<<<SEQ, HD / 2>>>();

    split_kernel<<<(MTOT * DM) / 256, 256>>>(x, pxs, MTOT * DM);
    split_kernel<<<(DM * DM) / 256, 256>>>(Wq, pws + 0ULL * DM * K3, DM * DM);
    split_kernel<<<(DM * DM) / 256, 256>>>(Wk, pws + 1ULL * DM * K3, DM * DM);
    split_kernel<<<(DM * DM) / 256, 256>>>(Wv, pws + 2ULL * DM * K3, DM * DM);
    split_kernel<<<(DM * DM) / 256, 256>>>(Wo, pws + 3ULL * DM * K3, DM * DM);

    // QKV: z=2 (V) writes bf16 splits directly
    mma_gemm2_kernel<<<dim3(16, 16, 3), 256, GEMM2_SMEM>>>(
        pxs, pws + 0ULL * DM * K3, pws + 1ULL * DM * K3, pws + 2ULL * DM * K3,
        pq, pk, pq, 1);

    rope_apply_kernel<<<(MTOT * (DM / 2)) / 256, 256>>>();

    // fused attention (scores + softmax + PV)
    flash_kernel<<<dim3(16, 32), 256, FLASH_SMEM>>>();

    // out-projection from fused attn-out split
    mma_gemm2_kernel<<<dim3(16, 16, 1), 256, GEMM2_SMEM>>>(
        paos, pws + 3ULL * DM * K3, pws + 3ULL * DM * K3, pws + 3ULL * DM * K3,
        out, out, out, 0);
}